// round 11
// baseline (speedup 1.0000x reference)
#include <cuda_runtime.h>
#include <cuda_bf16.h>
#include <math.h>

#define NN 50000
#define NE 800000
#define C  128

// ---------------- device scratch ----------------
static __device__ float g_P1[(size_t)NN * C];    // nf @ W1a
static __device__ float g_P2[(size_t)NN * C];    // nf @ W1b
static __device__ float g_t1[(size_t)NN * C];    // node hidden
static __device__ float g_hneigh[(size_t)NN * C];
static __device__ float g_xsum[NN * 3];
static __device__ float g_deg[NN];
static __device__ float g_red[16];

__device__ __forceinline__ float silu_f(float v) {
    return v / (1.0f + __expf(-v));
}
__device__ __forceinline__ float tf32f(float x) {
    unsigned u;
    asm("cvt.rna.tf32.f32 %0, %1;" : "=r"(u) : "f"(x));
    return __uint_as_float(u);
}
__device__ __forceinline__ unsigned fu(float x) { return __float_as_uint(x); }

__device__ __forceinline__ void mma8(float* d, const unsigned* a, unsigned b0, unsigned b1) {
    asm volatile(
        "mma.sync.aligned.m16n8k8.row.col.f32.tf32.tf32.f32 "
        "{%0,%1,%2,%3}, {%4,%5,%6,%7}, {%8,%9}, {%0,%1,%2,%3};"
        : "+f"(d[0]), "+f"(d[1]), "+f"(d[2]), "+f"(d[3])
        : "r"(a[0]), "r"(a[1]), "r"(a[2]), "r"(a[3]), "r"(b0), "r"(b1));
}

// =============== paired-k W layout ===============
// sWp[(kc*128 + c)*8 + 2*(k&3) + ((k>>2)&1)] holds W[k][c], kc = k>>3.
// B-fragment (k=t, k=t+4) for col c is one aligned float2.

// Warp-tile GEMM for node kernels: A row-major in smem, B paired; warp =
// 32 rows x NI*8 cols at row wr*32, col wc*NI*8.
template<int SA, bool CVTA, int NI>
__device__ __forceinline__ void gemm_rApB(const float* __restrict__ sA,
                                          const float* __restrict__ sWp,
                                          int kchunks, float (&acc)[2][NI][4],
                                          int wr, int wc, int lane) {
    const int g = lane >> 2, t = lane & 3;
    const float* ar = sA + (wr * 32 + g) * SA + t;
    const float* bb = sWp + (wc * (NI * 8) + g) * 8 + 2 * t;
#pragma unroll 4
    for (int kc = 0; kc < kchunks; ++kc) {
        const float* ap = ar + kc * 8;
        float a00 = ap[0],       a01 = ap[8 * SA],       a02 = ap[4],       a03 = ap[8 * SA + 4];
        float a10 = ap[16 * SA], a11 = ap[24 * SA],      a12 = ap[16 * SA + 4], a13 = ap[24 * SA + 4];
        if (CVTA) {
            a00 = tf32f(a00); a01 = tf32f(a01); a02 = tf32f(a02); a03 = tf32f(a03);
            a10 = tf32f(a10); a11 = tf32f(a11); a12 = tf32f(a12); a13 = tf32f(a13);
        }
        unsigned A0[4] = {fu(a00), fu(a01), fu(a02), fu(a03)};
        unsigned A1[4] = {fu(a10), fu(a11), fu(a12), fu(a13)};
        const float* bp = bb + kc * 1024;
#pragma unroll
        for (int ni = 0; ni < NI; ++ni) {
            float2 b = *(const float2*)(bp + ni * 64);
            mma8(acc[0][ni], A0, fu(b.x), fu(b.y));
            mma8(acc[1][ni], A1, fu(b.x), fu(b.y));
        }
    }
}

// load W[16384] (row-major [128][128]) into paired layout with tf32 rounding
__device__ __forceinline__ void load_paired(float* sWp, const float* W, int tid, int nthr) {
    for (int i = tid; i < 16384; i += nthr) {
        int k = i >> 7, c = i & 127;
        int pos = ((k >> 3) * 128 + c) * 8 + 2 * (k & 3) + ((k >> 2) & 1);
        sWp[pos] = tf32f(W[i]);
    }
}

// ---------------- k_init ----------------
__global__ void k_init() {
    const long NC = (long)NN * C, N3 = NN * 3;
    const long TOT = NC + N3 + NN + 16;
    long stride = (long)gridDim.x * blockDim.x;
    for (long i = (long)blockIdx.x * blockDim.x + threadIdx.x; i < TOT; i += stride) {
        if (i < NC) g_hneigh[i] = 0.f;
        else if (i < NC + N3) g_xsum[i - NC] = 0.f;
        else if (i < NC + N3 + NN) g_deg[i - NC - N3] = 0.f;
        else g_red[i - NC - N3 - NN] = 0.f;
    }
}

// ---------------- k_npre: P1 = nf@W1a, P2 = nf@W1b ----------------
__global__ void __launch_bounds__(512, 1)
k_npre(const float* __restrict__ nf, const float* __restrict__ W1) {
    extern __shared__ float sm[];
    float* sWa = sm;                       // 16384 (paired)
    float* sWb = sWa + 16384;              // 16384 (paired)
    float* sA  = sWb + 16384;              // 128*132 = 16896

    const int tid = threadIdx.x, lane = tid & 31, wid = tid >> 5;
    const int wr = wid & 3, wc = wid >> 2;
    const int g = lane >> 2, t = lane & 3;

    load_paired(sWa, W1, tid, 512);
    load_paired(sWb, W1 + 16384, tid, 512);
    __syncthreads();

    const int ntiles = (NN + 127) / 128;
    for (int tile = blockIdx.x; tile < ntiles; tile += gridDim.x) {
        const int bn = tile * 128;
        for (int i = tid; i < 4096; i += 512) {
            int row = i >> 5, c4 = (i & 31) * 4;
            int n = bn + row;
            float4 v = make_float4(0.f, 0.f, 0.f, 0.f);
            if (n < NN) v = *(const float4*)&nf[(size_t)n * 128 + c4];
            float* p = &sA[row * 132 + c4];
            p[0] = tf32f(v.x); p[1] = tf32f(v.y); p[2] = tf32f(v.z); p[3] = tf32f(v.w);
        }
        __syncthreads();

        float acc[2][4][4];
#pragma unroll
        for (int mi = 0; mi < 2; ++mi)
#pragma unroll
            for (int ni = 0; ni < 4; ++ni)
#pragma unroll
                for (int q = 0; q < 4; ++q) acc[mi][ni][q] = 0.f;
        gemm_rApB<132, false, 4>(sA, sWa, 16, acc, wr, wc, lane);
#pragma unroll
        for (int mi = 0; mi < 2; ++mi) {
            int r = bn + wr * 32 + mi * 16 + g;
#pragma unroll
            for (int ni = 0; ni < 4; ++ni) {
                int c = wc * 32 + ni * 8 + 2 * t;
                if (r < NN)
                    *(float2*)&g_P1[(size_t)r * 128 + c] = make_float2(acc[mi][ni][0], acc[mi][ni][1]);
                if (r + 8 < NN)
                    *(float2*)&g_P1[(size_t)(r + 8) * 128 + c] = make_float2(acc[mi][ni][2], acc[mi][ni][3]);
            }
        }
#pragma unroll
        for (int mi = 0; mi < 2; ++mi)
#pragma unroll
            for (int ni = 0; ni < 4; ++ni)
#pragma unroll
                for (int q = 0; q < 4; ++q) acc[mi][ni][q] = 0.f;
        gemm_rApB<132, false, 4>(sA, sWb, 16, acc, wr, wc, lane);
#pragma unroll
        for (int mi = 0; mi < 2; ++mi) {
            int r = bn + wr * 32 + mi * 16 + g;
#pragma unroll
            for (int ni = 0; ni < 4; ++ni) {
                int c = wc * 32 + ni * 8 + 2 * t;
                if (r < NN)
                    *(float2*)&g_P2[(size_t)r * 128 + c] = make_float2(acc[mi][ni][0], acc[mi][ni][1]);
                if (r + 8 < NN)
                    *(float2*)&g_P2[(size_t)(r + 8) * 128 + c] = make_float2(acc[mi][ni][2], acc[mi][ni][3]);
            }
        }
        __syncthreads();
    }
}

// ---------------- k_edge: warp-private pipelines, ZERO barriers ----------------
// Each warp processes 16 edges end-to-end in a private 16x132 smem tile:
//   h1 = silu(P1[s]+P2[d]+r*wr+b1); h2 = silu(h1@W2+b2) -> scatter;
//   cw = silu(h2@W5+b5).W6 -> coord scatter.
__global__ void __launch_bounds__(256, 1)
k_edge(const float* __restrict__ coord,
       const int* __restrict__ src, const int* __restrict__ dst,
       const float* __restrict__ W1, const float* __restrict__ b1,
       const float* __restrict__ W2, const float* __restrict__ b2,
       const float* __restrict__ W5, const float* __restrict__ b5,
       const float* __restrict__ W6) {
    extern __shared__ float sm[];
    float* sW2p = sm;                      // 16384 (paired)
    float* sW5p = sW2p + 16384;            // 16384 (paired)
    float* sT0  = sW5p + 16384;            // 8 * 16*132 = 16896
    float* sWr  = sT0 + 16896;             // 128
    float* sB1  = sWr + 128;               // 128
    float* sB2  = sB1 + 128;               // 128
    float* sB5  = sB2 + 128;               // 128
    float* sW6  = sB5 + 128;               // 128

    const int tid = threadIdx.x, lane = tid & 31, wid = tid >> 5;
    const int g = lane >> 2, t = lane & 3;
    float* sT = sT0 + wid * 2112;          // warp-private 16x132

    load_paired(sW2p, W2, tid, 256);
    load_paired(sW5p, W5, tid, 256);
    if (tid < 128) {
        sWr[tid] = W1[256 * 128 + tid];
        sB1[tid] = b1[tid]; sB2[tid] = b2[tid]; sB5[tid] = b5[tid]; sW6[tid] = W6[tid];
    }
    __syncthreads();

    const float* bb2 = sW2p + g * 8 + 2 * t;
    const float* bb5 = sW5p + g * 8 + 2 * t;

    int se = 0, de = 0; float rr = 0.f;
    const int nch = NE / 16;               // 50000
    for (int ch = blockIdx.x * 8 + wid; ch < nch; ch += gridDim.x * 8) {
        const int be = ch * 16;
        if (lane < 16) {
            int e = be + lane;
            se = src[e]; de = dst[e];
            atomicAdd(&g_deg[de], 1.0f);
            float dx = coord[se * 3 + 0] - coord[de * 3 + 0];
            float dy = coord[se * 3 + 1] - coord[de * 3 + 1];
            float dz = coord[se * 3 + 2] - coord[de * 3 + 2];
            rr = dx * dx + dy * dy + dz * dz;
        }
        __syncwarp();                      // idx ready; prior-chunk sT reads done

        // gather-assemble h1: row j, this thread covers cols lane*4..+3
        const float4 w4 = *(const float4*)&sWr[lane * 4];
        const float4 bv = *(const float4*)&sB1[lane * 4];
#pragma unroll
        for (int j = 0; j < 16; ++j) {
            int s = __shfl_sync(0xffffffffu, se, j);
            int d = __shfl_sync(0xffffffffu, de, j);
            float r = __shfl_sync(0xffffffffu, rr, j);
            const float4 p1 = *(const float4*)&g_P1[(size_t)s * 128 + lane * 4];
            const float4 p2 = *(const float4*)&g_P2[(size_t)d * 128 + lane * 4];
            float4 o;
            o.x = tf32f(silu_f(p1.x + p2.x + r * w4.x + bv.x));
            o.y = tf32f(silu_f(p1.y + p2.y + r * w4.y + bv.y));
            o.z = tf32f(silu_f(p1.z + p2.z + r * w4.z + bv.z));
            o.w = tf32f(silu_f(p1.w + p2.w + r * w4.w + bv.w));
            *(float4*)&sT[j * 132 + lane * 4] = o;
        }
        __syncwarp();                      // h1 complete

        // GEMM1: h2pre = h1 @ W2 + b2 (16 rows x 128 cols, single warp)
        float acc[16][4];
#pragma unroll
        for (int ni = 0; ni < 16; ++ni) {
            float2 b = *(const float2*)&sB2[ni * 8 + 2 * t];
            acc[ni][0] = b.x; acc[ni][1] = b.y; acc[ni][2] = b.x; acc[ni][3] = b.y;
        }
        const float* ar = sT + g * 132 + t;
#pragma unroll 4
        for (int kc = 0; kc < 16; ++kc) {
            const float* ap = ar + kc * 8;
            unsigned A[4] = {fu(ap[0]), fu(ap[8 * 132]), fu(ap[4]), fu(ap[8 * 132 + 4])};
            const float* bp = bb2 + kc * 1024;
#pragma unroll
            for (int ni = 0; ni < 16; ++ni) {
                float2 b = *(const float2*)(bp + ni * 64);
                mma8(acc[ni], A, fu(b.x), fu(b.y));
            }
        }
        __syncwarp();                      // h1 reads done

        // write h2 = silu(acc) into sT (fp32)
#pragma unroll
        for (int ni = 0; ni < 16; ++ni) {
            *(float2*)&sT[g * 132 + ni * 8 + 2 * t] =
                make_float2(silu_f(acc[ni][0]), silu_f(acc[ni][1]));
            *(float2*)&sT[(g + 8) * 132 + ni * 8 + 2 * t] =
                make_float2(silu_f(acc[ni][2]), silu_f(acc[ni][3]));
        }
        __syncwarp();                      // h2 complete

        // GEMM2: h3pre = h2 @ W5 + b5 (tf32 cvt on A)
        float acc2[16][4];
#pragma unroll
        for (int ni = 0; ni < 16; ++ni) {
            float2 b = *(const float2*)&sB5[ni * 8 + 2 * t];
            acc2[ni][0] = b.x; acc2[ni][1] = b.y; acc2[ni][2] = b.x; acc2[ni][3] = b.y;
        }
#pragma unroll 4
        for (int kc = 0; kc < 16; ++kc) {
            const float* ap = ar + kc * 8;
            unsigned A[4] = {fu(tf32f(ap[0])), fu(tf32f(ap[8 * 132])),
                             fu(tf32f(ap[4])), fu(tf32f(ap[8 * 132 + 4]))};
            const float* bp = bb5 + kc * 1024;
#pragma unroll
            for (int ni = 0; ni < 16; ++ni) {
                float2 b = *(const float2*)(bp + ni * 64);
                mma8(acc2[ni], A, fu(b.x), fu(b.y));
            }
        }

        // scatter h2 -> g_hneigh (vector reduction atomics)
#pragma unroll
        for (int j = 0; j < 16; ++j) {
            int d = __shfl_sync(0xffffffffu, de, j);
            const float4 v = *(const float4*)&sT[j * 132 + lane * 4];
            float* p = &g_hneigh[(size_t)d * 128 + lane * 4];
            asm volatile("red.global.add.v4.f32 [%0], {%1,%2,%3,%4};"
                         :: "l"(p), "f"(v.x), "f"(v.y), "f"(v.z), "f"(v.w) : "memory");
        }

        // cw[row] = sum_c silu(h3pre)*W6[c]; rows g (cw0) and g+8 (cw1)
        float cw0 = 0.f, cw1 = 0.f;
#pragma unroll
        for (int ni = 0; ni < 16; ++ni) {
            float2 w6v = *(const float2*)&sW6[ni * 8 + 2 * t];
            cw0 += silu_f(acc2[ni][0]) * w6v.x + silu_f(acc2[ni][1]) * w6v.y;
            cw1 += silu_f(acc2[ni][2]) * w6v.x + silu_f(acc2[ni][3]) * w6v.y;
        }
        cw0 += __shfl_xor_sync(0xffffffffu, cw0, 1);
        cw0 += __shfl_xor_sync(0xffffffffu, cw0, 2);
        cw1 += __shfl_xor_sync(0xffffffffu, cw1, 1);
        cw1 += __shfl_xor_sync(0xffffffffu, cw1, 2);

        int s0 = __shfl_sync(0xffffffffu, se, g),     d0 = __shfl_sync(0xffffffffu, de, g);
        int s1 = __shfl_sync(0xffffffffu, se, g + 8), d1 = __shfl_sync(0xffffffffu, de, g + 8);
        if (t == 0) {
            {
                float dx = coord[s0 * 3 + 0] - coord[d0 * 3 + 0];
                float dy = coord[s0 * 3 + 1] - coord[d0 * 3 + 1];
                float dz = coord[s0 * 3 + 2] - coord[d0 * 3 + 2];
                float r  = dx * dx + dy * dy + dz * dz;
                float cws = cw0 / (sqrtf(r + 1e-6f) + 1e-6f);
                atomicAdd(&g_xsum[d0 * 3 + 0], cws * dx);
                atomicAdd(&g_xsum[d0 * 3 + 1], cws * dy);
                atomicAdd(&g_xsum[d0 * 3 + 2], cws * dz);
            }
            {
                float dx = coord[s1 * 3 + 0] - coord[d1 * 3 + 0];
                float dy = coord[s1 * 3 + 1] - coord[d1 * 3 + 1];
                float dz = coord[s1 * 3 + 2] - coord[d1 * 3 + 2];
                float r  = dx * dx + dy * dy + dz * dz;
                float cws = cw1 / (sqrtf(r + 1e-6f) + 1e-6f);
                atomicAdd(&g_xsum[d1 * 3 + 0], cws * dx);
                atomicAdd(&g_xsum[d1 * 3 + 1], cws * dy);
                atomicAdd(&g_xsum[d1 * 3 + 2], cws * dz);
            }
        }
        // next chunk's syncwarp gates sT reuse
    }
}

// ---------------- k_node1: t1 = silu([nf|h_neigh] @ W3 + b3) -> g_t1 ----------------
__global__ void __launch_bounds__(512, 1)
k_node1(const float* __restrict__ nf, const float* __restrict__ W3,
        const float* __restrict__ b3) {
    extern __shared__ float sm[];
    float* sWa = sm;                       // 16384 (paired)
    float* sWb = sWa + 16384;              // 16384 (paired)
    float* sA  = sWb + 16384;              // 128*132

    const int tid = threadIdx.x, lane = tid & 31, wid = tid >> 5;
    const int wr = wid & 3, wc = wid >> 2;
    const int g = lane >> 2, t = lane & 3;

    load_paired(sWa, W3, tid, 512);
    load_paired(sWb, W3 + 16384, tid, 512);
    __syncthreads();

    float blo[4], bhi[4];
    {
        int cb = wc * 32 + 2 * t;
#pragma unroll
        for (int ni = 0; ni < 4; ++ni) {
            blo[ni] = __ldg(&b3[cb + ni * 8]);
            bhi[ni] = __ldg(&b3[cb + ni * 8 + 1]);
        }
    }

    const int ntiles = (NN + 127) / 128;
    for (int tile = blockIdx.x; tile < ntiles; tile += gridDim.x) {
        const int bn = tile * 128;
        for (int i = tid; i < 4096; i += 512) {
            int row = i >> 5, c4 = (i & 31) * 4;
            int n = bn + row;
            float4 v = make_float4(0.f, 0.f, 0.f, 0.f);
            if (n < NN) v = *(const float4*)&nf[(size_t)n * 128 + c4];
            float* p = &sA[row * 132 + c4];
            p[0] = tf32f(v.x); p[1] = tf32f(v.y); p[2] = tf32f(v.z); p[3] = tf32f(v.w);
        }
        __syncthreads();

        float acc[2][4][4];
#pragma unroll
        for (int mi = 0; mi < 2; ++mi)
#pragma unroll
            for (int ni = 0; ni < 4; ++ni) {
                acc[mi][ni][0] = blo[ni]; acc[mi][ni][1] = bhi[ni];
                acc[mi][ni][2] = blo[ni]; acc[mi][ni][3] = bhi[ni];
            }
        gemm_rApB<132, false, 4>(sA, sWa, 16, acc, wr, wc, lane);
        __syncthreads();
        for (int i = tid; i < 4096; i += 512) {
            int row = i >> 5, c4 = (i & 31) * 4;
            int n = bn + row;
            float4 v = make_float4(0.f, 0.f, 0.f, 0.f);
            if (n < NN) v = *(const float4*)&g_hneigh[(size_t)n * 128 + c4];
            float* p = &sA[row * 132 + c4];
            p[0] = tf32f(v.x); p[1] = tf32f(v.y); p[2] = tf32f(v.z); p[3] = tf32f(v.w);
        }
        __syncthreads();
        gemm_rApB<132, false, 4>(sA, sWb, 16, acc, wr, wc, lane);

#pragma unroll
        for (int mi = 0; mi < 2; ++mi) {
            int r = bn + wr * 32 + mi * 16 + g;
#pragma unroll
            for (int ni = 0; ni < 4; ++ni) {
                int c = wc * 32 + ni * 8 + 2 * t;
                if (r < NN)
                    *(float2*)&g_t1[(size_t)r * 128 + c] =
                        make_float2(tf32f(silu_f(acc[mi][ni][0])), tf32f(silu_f(acc[mi][ni][1])));
                if (r + 8 < NN)
                    *(float2*)&g_t1[(size_t)(r + 8) * 128 + c] =
                        make_float2(tf32f(silu_f(acc[mi][ni][2])), tf32f(silu_f(acc[mi][ni][3])));
            }
        }
        __syncthreads();
    }
}

// ---------------- k_node2: h = t1 @ W4 + b4 -> out ----------------
__global__ void __launch_bounds__(512, 1)
k_node2(const float* __restrict__ W4, const float* __restrict__ b4,
        float* __restrict__ outh) {
    extern __shared__ float sm[];
    float* sW = sm;                        // 16384 (paired)
    float* sA = sW + 16384;                // 128*132

    const int tid = threadIdx.x, lane = tid & 31, wid = tid >> 5;
    const int wr = wid & 3, wc = wid >> 2;
    const int g = lane >> 2, t = lane & 3;

    load_paired(sW, W4, tid, 512);
    __syncthreads();

    float blo[4], bhi[4];
    {
        int cb = wc * 32 + 2 * t;
#pragma unroll
        for (int ni = 0; ni < 4; ++ni) {
            blo[ni] = __ldg(&b4[cb + ni * 8]);
            bhi[ni] = __ldg(&b4[cb + ni * 8 + 1]);
        }
    }

    const int ntiles = (NN + 127) / 128;
    for (int tile = blockIdx.x; tile < ntiles; tile += gridDim.x) {
        const int bn = tile * 128;
        for (int i = tid; i < 4096; i += 512) {
            int row = i >> 5, c4 = (i & 31) * 4;
            int n = bn + row;
            float4 v = make_float4(0.f, 0.f, 0.f, 0.f);
            if (n < NN) v = *(const float4*)&g_t1[(size_t)n * 128 + c4];
            *(float4*)&sA[row * 132 + c4] = v;
        }
        __syncthreads();

        float acc[2][4][4];
#pragma unroll
        for (int mi = 0; mi < 2; ++mi)
#pragma unroll
            for (int ni = 0; ni < 4; ++ni) {
                acc[mi][ni][0] = blo[ni]; acc[mi][ni][1] = bhi[ni];
                acc[mi][ni][2] = blo[ni]; acc[mi][ni][3] = bhi[ni];
            }
        gemm_rApB<132, false, 4>(sA, sW, 16, acc, wr, wc, lane);

#pragma unroll
        for (int mi = 0; mi < 2; ++mi) {
            int r = bn + wr * 32 + mi * 16 + g;
#pragma unroll
            for (int ni = 0; ni < 4; ++ni) {
                int c = wc * 32 + ni * 8 + 2 * t;
                if (r < NN)
                    *(float2*)&outh[(size_t)r * 128 + c] =
                        make_float2(acc[mi][ni][0], acc[mi][ni][1]);
                if (r + 8 < NN)
                    *(float2*)&outh[(size_t)(r + 8) * 128 + c] =
                        make_float2(acc[mi][ni][2], acc[mi][ni][3]);
            }
        }
        __syncthreads();
    }
}

// ---------------- k_x / k_fin / k_norm ----------------
__global__ void k_x(const float* __restrict__ coord, float* __restrict__ outx) {
    __shared__ float sred[6];
    int tid = threadIdx.x;
    if (tid < 6) sred[tid] = 0.f;
    __syncthreads();
    float ls[6] = {0.f, 0.f, 0.f, 0.f, 0.f, 0.f};
    int stride = gridDim.x * blockDim.x;
    for (int n = blockIdx.x * blockDim.x + tid; n < NN; n += stride) {
        float deg = fmaxf(g_deg[n], 1.0f);
        float invd = 1.0f / deg;
#pragma unroll
        for (int d = 0; d < 3; ++d) {
            float x = coord[n * 3 + d] + g_xsum[n * 3 + d] * invd;
            outx[n * 3 + d] = x;
            ls[d] += x;
            ls[3 + d] += x * x;
        }
    }
#pragma unroll
    for (int k = 0; k < 6; ++k) atomicAdd(&sred[k], ls[k]);
    __syncthreads();
    if (tid < 6) atomicAdd(&g_red[tid], sred[tid]);
}

__global__ void k_fin() {
    int t = threadIdx.x;
    if (t < 3) {
        float mean = g_red[t] / (float)NN;
        float m2   = g_red[3 + t] / (float)NN;
        float var  = m2 - mean * mean;
        g_red[8 + t]  = mean;
        g_red[11 + t] = 1.0f / (sqrtf(var + 1e-6f) + 1e-6f);
    }
}

__global__ void k_norm(float* __restrict__ outx) {
    int stride = gridDim.x * blockDim.x;
    for (int i = blockIdx.x * blockDim.x + threadIdx.x; i < NN * 3; i += stride) {
        int d = i % 3;
        outx[i] = (outx[i] - g_red[8 + d]) * g_red[11 + d];
    }
}

// ---------------- launch ----------------
extern "C" void kernel_launch(void* const* d_in, const int* in_sizes, int n_in,
                              void* d_out, int out_size) {
    const float* nf    = (const float*)d_in[0];
    const float* coord = (const float*)d_in[1];
    const int*   src   = (const int*)d_in[2];
    const int*   dst   = (const int*)d_in[3];
    const float* W1 = (const float*)d_in[4];
    const float* b1 = (const float*)d_in[5];
    const float* W2 = (const float*)d_in[6];
    const float* b2 = (const float*)d_in[7];
    const float* W3 = (const float*)d_in[8];
    const float* b3 = (const float*)d_in[9];
    const float* W4 = (const float*)d_in[10];
    const float* b4 = (const float*)d_in[11];
    const float* W5 = (const float*)d_in[12];
    const float* b5 = (const float*)d_in[13];
    const float* W6 = (const float*)d_in[14];

    float* outh = (float*)d_out;
    float* outx = outh + (size_t)NN * C;

    const int SM_NPRE = (16384 * 2 + 16896) * 4;
    const int SM_EDGE = (16384 * 2 + 16896 + 128 * 5) * 4;
    const int SM_N1   = (16384 * 2 + 16896) * 4;
    const int SM_N2   = (16384 + 16896) * 4;

    cudaFuncSetAttribute(k_npre,  cudaFuncAttributeMaxDynamicSharedMemorySize, SM_NPRE);
    cudaFuncSetAttribute(k_edge,  cudaFuncAttributeMaxDynamicSharedMemorySize, SM_EDGE);
    cudaFuncSetAttribute(k_node1, cudaFuncAttributeMaxDynamicSharedMemorySize, SM_N1);
    cudaFuncSetAttribute(k_node2, cudaFuncAttributeMaxDynamicSharedMemorySize, SM_N2);

    k_init<<<2048, 256>>>();
    k_npre<<<148, 512, SM_NPRE>>>(nf, W1);
    k_edge<<<148, 256, SM_EDGE>>>(coord, src, dst, W1, b1, W2, b2, W5, b5, W6);
    k_node1<<<148, 512, SM_N1>>>(nf, W3, b3);
    k_node2<<<148, 512, SM_N2>>>(W4, b4, outh);
    k_x<<<160, 256>>>(coord, outx);
    k_fin<<<1, 32>>>();
    k_norm<<<160, 256>>>(outx);
}

// round 12
// speedup vs baseline: 1.5595x; 1.5595x over previous
#include <cuda_runtime.h>
#include <cuda_bf16.h>
#include <math.h>

#define NN 50000
#define NE 800000
#define C  128

// ---------------- device scratch ----------------
static __device__ float g_P1[(size_t)NN * C];    // nf @ W1a
static __device__ float g_P2[(size_t)NN * C];    // nf @ W1b
static __device__ float g_t1[(size_t)NN * C];    // node hidden
static __device__ float g_hneigh[(size_t)NN * C];
static __device__ float g_xsum[NN * 3];
static __device__ float g_deg[NN];
static __device__ float g_red[16];

__device__ __forceinline__ float silu_f(float v) {
    return v / (1.0f + __expf(-v));
}
__device__ __forceinline__ float tf32f(float x) {
    unsigned u;
    asm("cvt.rna.tf32.f32 %0, %1;" : "=r"(u) : "f"(x));
    return __uint_as_float(u);
}
__device__ __forceinline__ unsigned fu(float x) { return __float_as_uint(x); }

__device__ __forceinline__ void mma8(float* d, const unsigned* a, unsigned b0, unsigned b1) {
    asm volatile(
        "mma.sync.aligned.m16n8k8.row.col.f32.tf32.tf32.f32 "
        "{%0,%1,%2,%3}, {%4,%5,%6,%7}, {%8,%9}, {%0,%1,%2,%3};"
        : "+f"(d[0]), "+f"(d[1]), "+f"(d[2]), "+f"(d[3])
        : "r"(a[0]), "r"(a[1]), "r"(a[2]), "r"(a[3]), "r"(b0), "r"(b1));
}

#define GBAR(gr) asm volatile("bar.sync %0, 128;" :: "r"((gr) + 1) : "memory")

// =============== paired-k W layout ===============
// sWp[(kc*128 + c)*8 + 2*(k&3) + ((k>>2)&1)] holds W[k][c], kc = k>>3.
// B-fragment (k=t, k=t+4) for col c is one aligned float2.

// Warp-tile GEMM: A row-major in smem (optional tf32 cvt), B paired.
// Warp computes 32 rows x NI*8 cols (col base wc*NI*8), starting row wr*32.
template<int SA, bool CVTA, int NI>
__device__ __forceinline__ void gemm_rApB(const float* __restrict__ sA,
                                          const float* __restrict__ sWp,
                                          int kchunks, float (&acc)[2][NI][4],
                                          int wr, int wc, int lane) {
    const int g = lane >> 2, t = lane & 3;
    const float* ar = sA + (wr * 32 + g) * SA + t;
    const float* bb = sWp + (wc * (NI * 8) + g) * 8 + 2 * t;
#pragma unroll 4
    for (int kc = 0; kc < kchunks; ++kc) {
        const float* ap = ar + kc * 8;
        float a00 = ap[0],       a01 = ap[8 * SA],       a02 = ap[4],       a03 = ap[8 * SA + 4];
        float a10 = ap[16 * SA], a11 = ap[24 * SA],      a12 = ap[16 * SA + 4], a13 = ap[24 * SA + 4];
        if (CVTA) {
            a00 = tf32f(a00); a01 = tf32f(a01); a02 = tf32f(a02); a03 = tf32f(a03);
            a10 = tf32f(a10); a11 = tf32f(a11); a12 = tf32f(a12); a13 = tf32f(a13);
        }
        unsigned A0[4] = {fu(a00), fu(a01), fu(a02), fu(a03)};
        unsigned A1[4] = {fu(a10), fu(a11), fu(a12), fu(a13)};
        const float* bp = bb + kc * 1024;
#pragma unroll
        for (int ni = 0; ni < NI; ++ni) {
            float2 b = *(const float2*)(bp + ni * 64);
            mma8(acc[0][ni], A0, fu(b.x), fu(b.y));
            mma8(acc[1][ni], A1, fu(b.x), fu(b.y));
        }
    }
}

// load W[16384] (row-major [128][128]) into paired layout with tf32 rounding
__device__ __forceinline__ void load_paired(float* sWp, const float* W, int tid, int nthr) {
    for (int i = tid; i < 16384; i += nthr) {
        int k = i >> 7, c = i & 127;
        int pos = ((k >> 3) * 128 + c) * 8 + 2 * (k & 3) + ((k >> 2) & 1);
        sWp[pos] = tf32f(W[i]);
    }
}

// ---------------- k_init ----------------
__global__ void k_init() {
    const long NC = (long)NN * C, N3 = NN * 3;
    const long TOT = NC + N3 + NN + 16;
    long stride = (long)gridDim.x * blockDim.x;
    for (long i = (long)blockIdx.x * blockDim.x + threadIdx.x; i < TOT; i += stride) {
        if (i < NC) g_hneigh[i] = 0.f;
        else if (i < NC + N3) g_xsum[i - NC] = 0.f;
        else if (i < NC + N3 + NN) g_deg[i - NC - N3] = 0.f;
        else g_red[i - NC - N3 - NN] = 0.f;
    }
}

// ---------------- k_npre: P1 = nf@W1a, P2 = nf@W1b ----------------
__global__ void __launch_bounds__(512, 1)
k_npre(const float* __restrict__ nf, const float* __restrict__ W1) {
    extern __shared__ float sm[];
    float* sWa = sm;                       // 16384 (paired)
    float* sWb = sWa + 16384;              // 16384 (paired)
    float* sA  = sWb + 16384;              // 128*132 = 16896

    const int tid = threadIdx.x, lane = tid & 31, wid = tid >> 5;
    const int wr = wid & 3, wc = wid >> 2;
    const int g = lane >> 2, t = lane & 3;

    load_paired(sWa, W1, tid, 512);
    load_paired(sWb, W1 + 16384, tid, 512);
    __syncthreads();

    const int ntiles = (NN + 127) / 128;
    for (int tile = blockIdx.x; tile < ntiles; tile += gridDim.x) {
        const int bn = tile * 128;
        for (int i = tid; i < 4096; i += 512) {
            int row = i >> 5, c4 = (i & 31) * 4;
            int n = bn + row;
            float4 v = make_float4(0.f, 0.f, 0.f, 0.f);
            if (n < NN) v = *(const float4*)&nf[(size_t)n * 128 + c4];
            float* p = &sA[row * 132 + c4];
            p[0] = tf32f(v.x); p[1] = tf32f(v.y); p[2] = tf32f(v.z); p[3] = tf32f(v.w);
        }
        __syncthreads();

        float acc[2][4][4];
#pragma unroll
        for (int mi = 0; mi < 2; ++mi)
#pragma unroll
            for (int ni = 0; ni < 4; ++ni)
#pragma unroll
                for (int q = 0; q < 4; ++q) acc[mi][ni][q] = 0.f;
        gemm_rApB<132, false, 4>(sA, sWa, 16, acc, wr, wc, lane);
#pragma unroll
        for (int mi = 0; mi < 2; ++mi) {
            int r = bn + wr * 32 + mi * 16 + g;
#pragma unroll
            for (int ni = 0; ni < 4; ++ni) {
                int c = wc * 32 + ni * 8 + 2 * t;
                if (r < NN)
                    *(float2*)&g_P1[(size_t)r * 128 + c] = make_float2(acc[mi][ni][0], acc[mi][ni][1]);
                if (r + 8 < NN)
                    *(float2*)&g_P1[(size_t)(r + 8) * 128 + c] = make_float2(acc[mi][ni][2], acc[mi][ni][3]);
            }
        }
#pragma unroll
        for (int mi = 0; mi < 2; ++mi)
#pragma unroll
            for (int ni = 0; ni < 4; ++ni)
#pragma unroll
                for (int q = 0; q < 4; ++q) acc[mi][ni][q] = 0.f;
        gemm_rApB<132, false, 4>(sA, sWb, 16, acc, wr, wc, lane);
#pragma unroll
        for (int mi = 0; mi < 2; ++mi) {
            int r = bn + wr * 32 + mi * 16 + g;
#pragma unroll
            for (int ni = 0; ni < 4; ++ni) {
                int c = wc * 32 + ni * 8 + 2 * t;
                if (r < NN)
                    *(float2*)&g_P2[(size_t)r * 128 + c] = make_float2(acc[mi][ni][0], acc[mi][ni][1]);
                if (r + 8 < NN)
                    *(float2*)&g_P2[(size_t)(r + 8) * 128 + c] = make_float2(acc[mi][ni][2], acc[mi][ni][3]);
            }
        }
        __syncthreads();
    }
}

// ---------------- k_edge: 4 groups, register-resident edge metadata ----------------
// Group gr (4 warps, one per SMSP) processes 32-edge chunks. Every warp of the
// group redundantly holds the chunk's src/dst/coord-diff in per-lane registers
// (lane e owns edge be+e), so idx staging and the loop-top barrier vanish.
//   h1 = silu(P1[s]+P2[d]+r*wr+b1); h2 = silu(h1@W2+b2) -> scatter;
//   cw = silu(h2@W5+b5).W6 -> coord scatter.
__global__ void __launch_bounds__(512, 1)
k_edge(const float* __restrict__ coord,
       const int* __restrict__ src, const int* __restrict__ dst,
       const float* __restrict__ W1, const float* __restrict__ b1,
       const float* __restrict__ W2, const float* __restrict__ b2,
       const float* __restrict__ W5, const float* __restrict__ b5,
       const float* __restrict__ W6) {
    extern __shared__ float sm[];
    float* sW2p = sm;                      // 16384 (paired)
    float* sW5p = sW2p + 16384;            // 16384 (paired)
    float* sAall = sW5p + 16384;           // 4 * 32*132 = 16896
    float* sWr  = sAall + 16896;           // 128
    float* sB1  = sWr + 128;               // 128
    float* sCWA = sB1 + 128;               // 4 groups * 2 buf * 32 = 256

    const int tid = threadIdx.x, lane = tid & 31, wid = tid >> 5;
    const int gr = wid >> 2;               // group 0..3 (4 warps across 4 SMSPs)
    const int wc = wid & 3;                // column warp within group
    const int g = lane >> 2, t = lane & 3;
    const int gt = wc * 32 + lane;         // group-local thread 0..127

    float* sA  = sAall + gr * 4224;        // 32*132 per group
    float* sCW = sCWA + gr * 64;           // 2 x 32 double buffer

    load_paired(sW2p, W2, tid, 512);
    load_paired(sW5p, W5, tid, 512);
    if (tid < 128) { sWr[tid] = W1[256 * 128 + tid]; sB1[tid] = b1[tid]; }
    if (tid < 256) sCWA[tid] = 0.f;
    __syncthreads();

    float b2lo[4], b2hi[4], b5lo[4], b5hi[4], w6lo[4], w6hi[4];
    {
        int cb = wc * 32 + 2 * t;
#pragma unroll
        for (int ni = 0; ni < 4; ++ni) {
            b2lo[ni] = __ldg(&b2[cb + ni * 8]); b2hi[ni] = __ldg(&b2[cb + ni * 8 + 1]);
            b5lo[ni] = __ldg(&b5[cb + ni * 8]); b5hi[ni] = __ldg(&b5[cb + ni * 8 + 1]);
            w6lo[ni] = __ldg(&W6[cb + ni * 8]); w6hi[ni] = __ldg(&W6[cb + ni * 8 + 1]);
        }
    }

    const int c4 = (gt & 31) * 4;          // this thread's column (fixed)
    const int r0 = gt >> 5;                // row phase (0..3)
    const float4 w4 = *(const float4*)&sWr[c4];
    const float4 bv = *(const float4*)&sB1[c4];

    const int nchunks = NE / 32;           // 25000
    const int gstride = gridDim.x * 4;
    int pp = 0;                            // sCW buffer parity
    for (int chunk = blockIdx.x * 4 + gr; chunk < nchunks; chunk += gstride, pp ^= 1) {
        const int be = chunk * 32;
        // every warp loads the chunk's 32 edges (lane e -> edge be+e)
        int e = be + lane;
        int se = __ldg(&src[e]), de = __ldg(&dst[e]);
        float dxr = coord[se * 3 + 0] - coord[de * 3 + 0];
        float dyr = coord[se * 3 + 1] - coord[de * 3 + 1];
        float dzr = coord[se * 3 + 2] - coord[de * 3 + 2];
        float rr = dxr * dxr + dyr * dyr + dzr * dzr;
        if (wc == 0) atomicAdd(&g_deg[de], 1.0f);

        // gather-assemble h1 (32x128) into sA, 4-row load batches for MLP
#pragma unroll
        for (int half = 0; half < 2; ++half) {
            float4 p1v[4], p2v[4]; float rv[4];
#pragma unroll
            for (int k = 0; k < 4; ++k) {
                int row = r0 + 4 * (half * 4 + k);
                int s = __shfl_sync(0xffffffffu, se, row);
                int d = __shfl_sync(0xffffffffu, de, row);
                rv[k] = __shfl_sync(0xffffffffu, rr, row);
                p1v[k] = *(const float4*)&g_P1[(size_t)s * 128 + c4];
                p2v[k] = *(const float4*)&g_P2[(size_t)d * 128 + c4];
            }
#pragma unroll
            for (int k = 0; k < 4; ++k) {
                int row = r0 + 4 * (half * 4 + k);
                float4 o;
                o.x = tf32f(silu_f(p1v[k].x + p2v[k].x + rv[k] * w4.x + bv.x));
                o.y = tf32f(silu_f(p1v[k].y + p2v[k].y + rv[k] * w4.y + bv.y));
                o.z = tf32f(silu_f(p1v[k].z + p2v[k].z + rv[k] * w4.z + bv.z));
                o.w = tf32f(silu_f(p1v[k].w + p2v[k].w + rv[k] * w4.w + bv.w));
                *(float4*)&sA[row * 132 + c4] = o;
            }
        }
        GBAR(gr);                          // (1) h1 complete

        // GEMM1: h2pre = h1 @ W2 + b2 (warp owns 32x32 block)
        float acc[2][4][4];
#pragma unroll
        for (int mi = 0; mi < 2; ++mi)
#pragma unroll
            for (int ni = 0; ni < 4; ++ni) {
                acc[mi][ni][0] = b2lo[ni]; acc[mi][ni][1] = b2hi[ni];
                acc[mi][ni][2] = b2lo[ni]; acc[mi][ni][3] = b2hi[ni];
            }
        gemm_rApB<132, false, 4>(sA, sW2p, 16, acc, 0, wc, lane);
        GBAR(gr);                          // (2) h1 reads done

        // write h2 = silu(acc) into sA
#pragma unroll
        for (int mi = 0; mi < 2; ++mi) {
            int r = mi * 16 + g;
#pragma unroll
            for (int ni = 0; ni < 4; ++ni) {
                int c = wc * 32 + ni * 8 + 2 * t;
                *(float2*)&sA[r * 132 + c] =
                    make_float2(silu_f(acc[mi][ni][0]), silu_f(acc[mi][ni][1]));
                *(float2*)&sA[(r + 8) * 132 + c] =
                    make_float2(silu_f(acc[mi][ni][2]), silu_f(acc[mi][ni][3]));
            }
        }
        GBAR(gr);                          // (3) h2 complete

        // GEMM2: h3pre = h2 @ W5 + b5 (cvt A)
        float acc2[2][4][4];
#pragma unroll
        for (int mi = 0; mi < 2; ++mi)
#pragma unroll
            for (int ni = 0; ni < 4; ++ni) {
                acc2[mi][ni][0] = b5lo[ni]; acc2[mi][ni][1] = b5hi[ni];
                acc2[mi][ni][2] = b5lo[ni]; acc2[mi][ni][3] = b5hi[ni];
            }
        gemm_rApB<132, true, 4>(sA, sW5p, 16, acc2, 0, wc, lane);

        // scatter h2 -> g_hneigh (vector reduction atomics)
#pragma unroll
        for (int k = 0; k < 8; ++k) {
            int row = r0 + 4 * k;
            int d = __shfl_sync(0xffffffffu, de, row);
            const float4 v = *(const float4*)&sA[row * 132 + c4];
            float* p = &g_hneigh[(size_t)d * 128 + c4];
            asm volatile("red.global.add.v4.f32 [%0], {%1,%2,%3,%4};"
                         :: "l"(p), "f"(v.x), "f"(v.y), "f"(v.z), "f"(v.w) : "memory");
        }

        // cw[row] = sum_c silu(h3pre)*W6[c]
#pragma unroll
        for (int mi = 0; mi < 2; ++mi) {
            float pr0 = 0.f, pr1 = 0.f;
#pragma unroll
            for (int ni = 0; ni < 4; ++ni) {
                pr0 += silu_f(acc2[mi][ni][0]) * w6lo[ni] + silu_f(acc2[mi][ni][1]) * w6hi[ni];
                pr1 += silu_f(acc2[mi][ni][2]) * w6lo[ni] + silu_f(acc2[mi][ni][3]) * w6hi[ni];
            }
            pr0 += __shfl_xor_sync(0xffffffffu, pr0, 1);
            pr0 += __shfl_xor_sync(0xffffffffu, pr0, 2);
            pr1 += __shfl_xor_sync(0xffffffffu, pr1, 1);
            pr1 += __shfl_xor_sync(0xffffffffu, pr1, 2);
            if (t == 0) {
                int r = mi * 16 + g;
                atomicAdd(&sCW[pp * 32 + r], pr0);
                atomicAdd(&sCW[pp * 32 + r + 8], pr1);
            }
        }
        GBAR(gr);                          // (4) sCW complete, sA reads done

        if (wc == 0) {
            float cw = sCW[pp * 32 + lane];
            sCW[pp * 32 + lane] = 0.f;     // re-zero for reuse in 2 chunks
            float inv = 1.0f / (sqrtf(rr + 1e-6f) + 1e-6f);
            float cws = cw * inv;
            atomicAdd(&g_xsum[de * 3 + 0], cws * dxr);
            atomicAdd(&g_xsum[de * 3 + 1], cws * dyr);
            atomicAdd(&g_xsum[de * 3 + 2], cws * dzr);
        }
        // no loop-top barrier: sA free after (4); sCW buffer pp reused only
        // after two more (4)-barriers, past the zeroing above.
    }
}

// ---------------- k_node1: t1 = silu([nf|h_neigh] @ W3 + b3) -> g_t1 ----------------
__global__ void __launch_bounds__(512, 1)
k_node1(const float* __restrict__ nf, const float* __restrict__ W3,
        const float* __restrict__ b3) {
    extern __shared__ float sm[];
    float* sWa = sm;                       // 16384 (paired)
    float* sWb = sWa + 16384;              // 16384 (paired)
    float* sA  = sWb + 16384;              // 128*132

    const int tid = threadIdx.x, lane = tid & 31, wid = tid >> 5;
    const int wr = wid & 3, wc = wid >> 2;
    const int g = lane >> 2, t = lane & 3;

    load_paired(sWa, W3, tid, 512);
    load_paired(sWb, W3 + 16384, tid, 512);
    __syncthreads();

    float blo[4], bhi[4];
    {
        int cb = wc * 32 + 2 * t;
#pragma unroll
        for (int ni = 0; ni < 4; ++ni) {
            blo[ni] = __ldg(&b3[cb + ni * 8]);
            bhi[ni] = __ldg(&b3[cb + ni * 8 + 1]);
        }
    }

    const int ntiles = (NN + 127) / 128;
    for (int tile = blockIdx.x; tile < ntiles; tile += gridDim.x) {
        const int bn = tile * 128;
        for (int i = tid; i < 4096; i += 512) {
            int row = i >> 5, c4 = (i & 31) * 4;
            int n = bn + row;
            float4 v = make_float4(0.f, 0.f, 0.f, 0.f);
            if (n < NN) v = *(const float4*)&nf[(size_t)n * 128 + c4];
            float* p = &sA[row * 132 + c4];
            p[0] = tf32f(v.x); p[1] = tf32f(v.y); p[2] = tf32f(v.z); p[3] = tf32f(v.w);
        }
        __syncthreads();

        float acc[2][4][4];
#pragma unroll
        for (int mi = 0; mi < 2; ++mi)
#pragma unroll
            for (int ni = 0; ni < 4; ++ni) {
                acc[mi][ni][0] = blo[ni]; acc[mi][ni][1] = bhi[ni];
                acc[mi][ni][2] = blo[ni]; acc[mi][ni][3] = bhi[ni];
            }
        gemm_rApB<132, false, 4>(sA, sWa, 16, acc, wr, wc, lane);
        __syncthreads();
        for (int i = tid; i < 4096; i += 512) {
            int row = i >> 5, c4 = (i & 31) * 4;
            int n = bn + row;
            float4 v = make_float4(0.f, 0.f, 0.f, 0.f);
            if (n < NN) v = *(const float4*)&g_hneigh[(size_t)n * 128 + c4];
            float* p = &sA[row * 132 + c4];
            p[0] = tf32f(v.x); p[1] = tf32f(v.y); p[2] = tf32f(v.z); p[3] = tf32f(v.w);
        }
        __syncthreads();
        gemm_rApB<132, false, 4>(sA, sWb, 16, acc, wr, wc, lane);

#pragma unroll
        for (int mi = 0; mi < 2; ++mi) {
            int r = bn + wr * 32 + mi * 16 + g;
#pragma unroll
            for (int ni = 0; ni < 4; ++ni) {
                int c = wc * 32 + ni * 8 + 2 * t;
                if (r < NN)
                    *(float2*)&g_t1[(size_t)r * 128 + c] =
                        make_float2(tf32f(silu_f(acc[mi][ni][0])), tf32f(silu_f(acc[mi][ni][1])));
                if (r + 8 < NN)
                    *(float2*)&g_t1[(size_t)(r + 8) * 128 + c] =
                        make_float2(tf32f(silu_f(acc[mi][ni][2])), tf32f(silu_f(acc[mi][ni][3])));
            }
        }
        __syncthreads();
    }
}

// ---------------- k_node2: h = t1 @ W4 + b4 -> out ----------------
__global__ void __launch_bounds__(512, 1)
k_node2(const float* __restrict__ W4, const float* __restrict__ b4,
        float* __restrict__ outh) {
    extern __shared__ float sm[];
    float* sW = sm;                        // 16384 (paired)
    float* sA = sW + 16384;                // 128*132

    const int tid = threadIdx.x, lane = tid & 31, wid = tid >> 5;
    const int wr = wid & 3, wc = wid >> 2;
    const int g = lane >> 2, t = lane & 3;

    load_paired(sW, W4, tid, 512);
    __syncthreads();

    float blo[4], bhi[4];
    {
        int cb = wc * 32 + 2 * t;
#pragma unroll
        for (int ni = 0; ni < 4; ++ni) {
            blo[ni] = __ldg(&b4[cb + ni * 8]);
            bhi[ni] = __ldg(&b4[cb + ni * 8 + 1]);
        }
    }

    const int ntiles = (NN + 127) / 128;
    for (int tile = blockIdx.x; tile < ntiles; tile += gridDim.x) {
        const int bn = tile * 128;
        for (int i = tid; i < 4096; i += 512) {
            int row = i >> 5, c4 = (i & 31) * 4;
            int n = bn + row;
            float4 v = make_float4(0.f, 0.f, 0.f, 0.f);
            if (n < NN) v = *(const float4*)&g_t1[(size_t)n * 128 + c4];
            *(float4*)&sA[row * 132 + c4] = v;
        }
        __syncthreads();

        float acc[2][4][4];
#pragma unroll
        for (int mi = 0; mi < 2; ++mi)
#pragma unroll
            for (int ni = 0; ni < 4; ++ni) {
                acc[mi][ni][0] = blo[ni]; acc[mi][ni][1] = bhi[ni];
                acc[mi][ni][2] = blo[ni]; acc[mi][ni][3] = bhi[ni];
            }
        gemm_rApB<132, false, 4>(sA, sW, 16, acc, wr, wc, lane);

#pragma unroll
        for (int mi = 0; mi < 2; ++mi) {
            int r = bn + wr * 32 + mi * 16 + g;
#pragma unroll
            for (int ni = 0; ni < 4; ++ni) {
                int c = wc * 32 + ni * 8 + 2 * t;
                if (r < NN)
                    *(float2*)&outh[(size_t)r * 128 + c] =
                        make_float2(acc[mi][ni][0], acc[mi][ni][1]);
                if (r + 8 < NN)
                    *(float2*)&outh[(size_t)(r + 8) * 128 + c] =
                        make_float2(acc[mi][ni][2], acc[mi][ni][3]);
            }
        }
        __syncthreads();
    }
}

// ---------------- k_x / k_fin / k_norm ----------------
__global__ void k_x(const float* __restrict__ coord, float* __restrict__ outx) {
    __shared__ float sred[6];
    int tid = threadIdx.x;
    if (tid < 6) sred[tid] = 0.f;
    __syncthreads();
    float ls[6] = {0.f, 0.f, 0.f, 0.f, 0.f, 0.f};
    int stride = gridDim.x * blockDim.x;
    for (int n = blockIdx.x * blockDim.x + tid; n < NN; n += stride) {
        float deg = fmaxf(g_deg[n], 1.0f);
        float invd = 1.0f / deg;
#pragma unroll
        for (int d = 0; d < 3; ++d) {
            float x = coord[n * 3 + d] + g_xsum[n * 3 + d] * invd;
            outx[n * 3 + d] = x;
            ls[d] += x;
            ls[3 + d] += x * x;
        }
    }
#pragma unroll
    for (int k = 0; k < 6; ++k) atomicAdd(&sred[k], ls[k]);
    __syncthreads();
    if (tid < 6) atomicAdd(&g_red[tid], sred[tid]);
}

__global__ void k_fin() {
    int t = threadIdx.x;
    if (t < 3) {
        float mean = g_red[t] / (float)NN;
        float m2   = g_red[3 + t] / (float)NN;
        float var  = m2 - mean * mean;
        g_red[8 + t]  = mean;
        g_red[11 + t] = 1.0f / (sqrtf(var + 1e-6f) + 1e-6f);
    }
}

__global__ void k_norm(float* __restrict__ outx) {
    int stride = gridDim.x * blockDim.x;
    for (int i = blockIdx.x * blockDim.x + threadIdx.x; i < NN * 3; i += stride) {
        int d = i % 3;
        outx[i] = (outx[i] - g_red[8 + d]) * g_red[11 + d];
    }
}

// ---------------- launch ----------------
extern "C" void kernel_launch(void* const* d_in, const int* in_sizes, int n_in,
                              void* d_out, int out_size) {
    const float* nf    = (const float*)d_in[0];
    const float* coord = (const float*)d_in[1];
    const int*   src   = (const int*)d_in[2];
    const int*   dst   = (const int*)d_in[3];
    const float* W1 = (const float*)d_in[4];
    const float* b1 = (const float*)d_in[5];
    const float* W2 = (const float*)d_in[6];
    const float* b2 = (const float*)d_in[7];
    const float* W3 = (const float*)d_in[8];
    const float* b3 = (const float*)d_in[9];
    const float* W4 = (const float*)d_in[10];
    const float* b4 = (const float*)d_in[11];
    const float* W5 = (const float*)d_in[12];
    const float* b5 = (const float*)d_in[13];
    const float* W6 = (const float*)d_in[14];

    float* outh = (float*)d_out;
    float* outx = outh + (size_t)NN * C;

    const int SM_NPRE = (16384 * 2 + 16896) * 4;
    const int SM_EDGE = (16384 * 2 + 16896 + 128 * 2 + 256) * 4;
    const int SM_N1   = (16384 * 2 + 16896) * 4;
    const int SM_N2   = (16384 + 16896) * 4;

    cudaFuncSetAttribute(k_npre,  cudaFuncAttributeMaxDynamicSharedMemorySize, SM_NPRE);
    cudaFuncSetAttribute(k_edge,  cudaFuncAttributeMaxDynamicSharedMemorySize, SM_EDGE);
    cudaFuncSetAttribute(k_node1, cudaFuncAttributeMaxDynamicSharedMemorySize, SM_N1);
    cudaFuncSetAttribute(k_node2, cudaFuncAttributeMaxDynamicSharedMemorySize, SM_N2);

    k_init<<<2048, 256>>>();
    k_npre<<<148, 512, SM_NPRE>>>(nf, W1);
    k_edge<<<148, 512, SM_EDGE>>>(coord, src, dst, W1, b1, W2, b2, W5, b5, W6);
    k_node1<<<148, 512, SM_N1>>>(nf, W3, b3);
    k_node2<<<148, 512, SM_N2>>>(W4, b4, outh);
    k_x<<<160, 256>>>(coord, outx);
    k_fin<<<1, 32>>>();
    k_norm<<<160, 256>>>(outx);
}

// round 13
// speedup vs baseline: 1.9568x; 1.2548x over previous
#include <cuda_runtime.h>
#include <cuda_bf16.h>
#include <math.h>

#define NN 50000
#define NE 800000
#define C  128

// ---------------- device scratch ----------------
static __device__ float g_P1[(size_t)NN * C];    // nf @ W1a
static __device__ float g_P2[(size_t)NN * C];    // nf @ W1b
static __device__ float g_t1[(size_t)NN * C];    // node hidden
static __device__ float g_hneigh[(size_t)NN * C];
static __device__ float g_xsum[NN * 3];
static __device__ float g_deg[NN];
static __device__ float g_red[16];

// silu via MUFU.TANH: sigma(x)=0.5*tanh(x/2)+0.5 -> silu=fma(h,tanh(h),h)
__device__ __forceinline__ float silu_f(float v) {
    float h = 0.5f * v, th;
    asm("tanh.approx.f32 %0, %1;" : "=f"(th) : "f"(h));
    return fmaf(h, th, h);
}
__device__ __forceinline__ float tf32f(float x) {
    unsigned u;
    asm("cvt.rna.tf32.f32 %0, %1;" : "=r"(u) : "f"(x));
    return __uint_as_float(u);
}
__device__ __forceinline__ unsigned fu(float x) { return __float_as_uint(x); }

__device__ __forceinline__ void mma8(float* d, const unsigned* a, unsigned b0, unsigned b1) {
    asm volatile(
        "mma.sync.aligned.m16n8k8.row.col.f32.tf32.tf32.f32 "
        "{%0,%1,%2,%3}, {%4,%5,%6,%7}, {%8,%9}, {%0,%1,%2,%3};"
        : "+f"(d[0]), "+f"(d[1]), "+f"(d[2]), "+f"(d[3])
        : "r"(a[0]), "r"(a[1]), "r"(a[2]), "r"(a[3]), "r"(b0), "r"(b1));
}

#define GBAR(gr) asm volatile("bar.sync %0, 128;" :: "r"((gr) + 1) : "memory")

// =============== paired-k W layout ===============
// sWp[(kc*128 + c)*8 + 2*(k&3) + ((k>>2)&1)] holds W[k][c], kc = k>>3.
// B-fragment (k=t, k=t+4) for col c is one aligned float2.

template<int SA, bool CVTA, int NI>
__device__ __forceinline__ void gemm_rApB(const float* __restrict__ sA,
                                          const float* __restrict__ sWp,
                                          int kchunks, float (&acc)[2][NI][4],
                                          int wr, int wc, int lane) {
    const int g = lane >> 2, t = lane & 3;
    const float* ar = sA + (wr * 32 + g) * SA + t;
    const float* bb = sWp + (wc * (NI * 8) + g) * 8 + 2 * t;
#pragma unroll 4
    for (int kc = 0; kc < kchunks; ++kc) {
        const float* ap = ar + kc * 8;
        float a00 = ap[0],       a01 = ap[8 * SA],       a02 = ap[4],       a03 = ap[8 * SA + 4];
        float a10 = ap[16 * SA], a11 = ap[24 * SA],      a12 = ap[16 * SA + 4], a13 = ap[24 * SA + 4];
        if (CVTA) {
            a00 = tf32f(a00); a01 = tf32f(a01); a02 = tf32f(a02); a03 = tf32f(a03);
            a10 = tf32f(a10); a11 = tf32f(a11); a12 = tf32f(a12); a13 = tf32f(a13);
        }
        unsigned A0[4] = {fu(a00), fu(a01), fu(a02), fu(a03)};
        unsigned A1[4] = {fu(a10), fu(a11), fu(a12), fu(a13)};
        const float* bp = bb + kc * 1024;
#pragma unroll
        for (int ni = 0; ni < NI; ++ni) {
            float2 b = *(const float2*)(bp + ni * 64);
            mma8(acc[0][ni], A0, fu(b.x), fu(b.y));
            mma8(acc[1][ni], A1, fu(b.x), fu(b.y));
        }
    }
}

// load W[16384] (row-major [128][128]) into paired layout with tf32 rounding
__device__ __forceinline__ void load_paired(float* sWp, const float* W, int tid, int nthr) {
    for (int i = tid; i < 16384; i += nthr) {
        int k = i >> 7, c = i & 127;
        int pos = ((k >> 3) * 128 + c) * 8 + 2 * (k & 3) + ((k >> 2) & 1);
        sWp[pos] = tf32f(W[i]);
    }
}

// ---------------- k_npre: zero accumulators (was k_init), then P1/P2 ----------------
__global__ void __launch_bounds__(512, 1)
k_npre(const float* __restrict__ nf, const float* __restrict__ W1) {
    extern __shared__ float sm[];
    float* sWa = sm;                       // 16384 (paired)
    float* sWb = sWa + 16384;              // 16384 (paired)
    float* sA  = sWb + 16384;              // 128*132 = 16896

    const int tid = threadIdx.x, lane = tid & 31, wid = tid >> 5;
    const int wr = wid & 3, wc = wid >> 2;
    const int g = lane >> 2, t = lane & 3;

    // zero accumulators (replaces k_init)
    {
        const long NC = (long)NN * C, N3 = NN * 3;
        const long TOT = NC + N3 + NN + 16;
        long stride = (long)gridDim.x * blockDim.x;
        for (long i = (long)blockIdx.x * blockDim.x + tid; i < TOT; i += stride) {
            if (i < NC) g_hneigh[i] = 0.f;
            else if (i < NC + N3) g_xsum[i - NC] = 0.f;
            else if (i < NC + N3 + NN) g_deg[i - NC - N3] = 0.f;
            else g_red[i - NC - N3 - NN] = 0.f;
        }
    }

    load_paired(sWa, W1, tid, 512);
    load_paired(sWb, W1 + 16384, tid, 512);
    __syncthreads();

    const int ntiles = (NN + 127) / 128;
    for (int tile = blockIdx.x; tile < ntiles; tile += gridDim.x) {
        const int bn = tile * 128;
        for (int i = tid; i < 4096; i += 512) {
            int row = i >> 5, c4 = (i & 31) * 4;
            int n = bn + row;
            float4 v = make_float4(0.f, 0.f, 0.f, 0.f);
            if (n < NN) v = *(const float4*)&nf[(size_t)n * 128 + c4];
            float* p = &sA[row * 132 + c4];
            p[0] = tf32f(v.x); p[1] = tf32f(v.y); p[2] = tf32f(v.z); p[3] = tf32f(v.w);
        }
        __syncthreads();

        float acc[2][4][4];
#pragma unroll
        for (int mi = 0; mi < 2; ++mi)
#pragma unroll
            for (int ni = 0; ni < 4; ++ni)
#pragma unroll
                for (int q = 0; q < 4; ++q) acc[mi][ni][q] = 0.f;
        gemm_rApB<132, false, 4>(sA, sWa, 16, acc, wr, wc, lane);
#pragma unroll
        for (int mi = 0; mi < 2; ++mi) {
            int r = bn + wr * 32 + mi * 16 + g;
#pragma unroll
            for (int ni = 0; ni < 4; ++ni) {
                int c = wc * 32 + ni * 8 + 2 * t;
                if (r < NN)
                    *(float2*)&g_P1[(size_t)r * 128 + c] = make_float2(acc[mi][ni][0], acc[mi][ni][1]);
                if (r + 8 < NN)
                    *(float2*)&g_P1[(size_t)(r + 8) * 128 + c] = make_float2(acc[mi][ni][2], acc[mi][ni][3]);
            }
        }
#pragma unroll
        for (int mi = 0; mi < 2; ++mi)
#pragma unroll
            for (int ni = 0; ni < 4; ++ni)
#pragma unroll
                for (int q = 0; q < 4; ++q) acc[mi][ni][q] = 0.f;
        gemm_rApB<132, false, 4>(sA, sWb, 16, acc, wr, wc, lane);
#pragma unroll
        for (int mi = 0; mi < 2; ++mi) {
            int r = bn + wr * 32 + mi * 16 + g;
#pragma unroll
            for (int ni = 0; ni < 4; ++ni) {
                int c = wc * 32 + ni * 8 + 2 * t;
                if (r < NN)
                    *(float2*)&g_P2[(size_t)r * 128 + c] = make_float2(acc[mi][ni][0], acc[mi][ni][1]);
                if (r + 8 < NN)
                    *(float2*)&g_P2[(size_t)(r + 8) * 128 + c] = make_float2(acc[mi][ni][2], acc[mi][ni][3]);
            }
        }
        __syncthreads();
    }
}

// ---------------- k_edge: 4 groups, register-resident edge metadata ----------------
__global__ void __launch_bounds__(512, 1)
k_edge(const float* __restrict__ coord,
       const int* __restrict__ src, const int* __restrict__ dst,
       const float* __restrict__ W1, const float* __restrict__ b1,
       const float* __restrict__ W2, const float* __restrict__ b2,
       const float* __restrict__ W5, const float* __restrict__ b5,
       const float* __restrict__ W6) {
    extern __shared__ float sm[];
    float* sW2p = sm;                      // 16384 (paired)
    float* sW5p = sW2p + 16384;            // 16384 (paired)
    float* sAall = sW5p + 16384;           // 4 * 32*132 = 16896
    float* sWr  = sAall + 16896;           // 128
    float* sB1  = sWr + 128;               // 128
    float* sCWA = sB1 + 128;               // 4 groups * 2 buf * 32 = 256

    const int tid = threadIdx.x, lane = tid & 31, wid = tid >> 5;
    const int gr = wid >> 2;               // group 0..3 (4 warps across 4 SMSPs)
    const int wc = wid & 3;                // column warp within group
    const int g = lane >> 2, t = lane & 3;
    const int gt = wc * 32 + lane;         // group-local thread 0..127

    float* sA  = sAall + gr * 4224;        // 32*132 per group
    float* sCW = sCWA + gr * 64;           // 2 x 32 double buffer

    load_paired(sW2p, W2, tid, 512);
    load_paired(sW5p, W5, tid, 512);
    if (tid < 128) { sWr[tid] = W1[256 * 128 + tid]; sB1[tid] = b1[tid]; }
    if (tid < 256) sCWA[tid] = 0.f;
    __syncthreads();

    float b2lo[4], b2hi[4], b5lo[4], b5hi[4], w6lo[4], w6hi[4];
    {
        int cb = wc * 32 + 2 * t;
#pragma unroll
        for (int ni = 0; ni < 4; ++ni) {
            b2lo[ni] = __ldg(&b2[cb + ni * 8]); b2hi[ni] = __ldg(&b2[cb + ni * 8 + 1]);
            b5lo[ni] = __ldg(&b5[cb + ni * 8]); b5hi[ni] = __ldg(&b5[cb + ni * 8 + 1]);
            w6lo[ni] = __ldg(&W6[cb + ni * 8]); w6hi[ni] = __ldg(&W6[cb + ni * 8 + 1]);
        }
    }

    const int c4 = (gt & 31) * 4;          // this thread's column (fixed)
    const int r0 = gt >> 5;                // row phase (0..3)
    const float4 w4 = *(const float4*)&sWr[c4];
    const float4 bv = *(const float4*)&sB1[c4];

    const int nchunks = NE / 32;           // 25000
    const int gstride = gridDim.x * 4;
    int pp = 0;                            // sCW buffer parity
    for (int chunk = blockIdx.x * 4 + gr; chunk < nchunks; chunk += gstride, pp ^= 1) {
        const int be = chunk * 32;
        // every warp loads the chunk's 32 edges (lane e -> edge be+e)
        int e = be + lane;
        int se = __ldg(&src[e]), de = __ldg(&dst[e]);
        float dxr = coord[se * 3 + 0] - coord[de * 3 + 0];
        float dyr = coord[se * 3 + 1] - coord[de * 3 + 1];
        float dzr = coord[se * 3 + 2] - coord[de * 3 + 2];
        float rr = dxr * dxr + dyr * dyr + dzr * dzr;
        if (wc == 0) atomicAdd(&g_deg[de], 1.0f);

        // gather-assemble h1 (32x128) into sA, 4-row load batches for MLP
#pragma unroll
        for (int half = 0; half < 2; ++half) {
            float4 p1v[4], p2v[4]; float rv[4];
#pragma unroll
            for (int k = 0; k < 4; ++k) {
                int row = r0 + 4 * (half * 4 + k);
                int s = __shfl_sync(0xffffffffu, se, row);
                int d = __shfl_sync(0xffffffffu, de, row);
                rv[k] = __shfl_sync(0xffffffffu, rr, row);
                p1v[k] = *(const float4*)&g_P1[(size_t)s * 128 + c4];
                p2v[k] = *(const float4*)&g_P2[(size_t)d * 128 + c4];
            }
#pragma unroll
            for (int k = 0; k < 4; ++k) {
                int row = r0 + 4 * (half * 4 + k);
                float4 o;
                o.x = tf32f(silu_f(p1v[k].x + p2v[k].x + rv[k] * w4.x + bv.x));
                o.y = tf32f(silu_f(p1v[k].y + p2v[k].y + rv[k] * w4.y + bv.y));
                o.z = tf32f(silu_f(p1v[k].z + p2v[k].z + rv[k] * w4.z + bv.z));
                o.w = tf32f(silu_f(p1v[k].w + p2v[k].w + rv[k] * w4.w + bv.w));
                *(float4*)&sA[row * 132 + c4] = o;
            }
        }
        GBAR(gr);                          // (1) h1 complete

        // GEMM1: h2pre = h1 @ W2 + b2 (warp owns 32x32 block)
        float acc[2][4][4];
#pragma unroll
        for (int mi = 0; mi < 2; ++mi)
#pragma unroll
            for (int ni = 0; ni < 4; ++ni) {
                acc[mi][ni][0] = b2lo[ni]; acc[mi][ni][1] = b2hi[ni];
                acc[mi][ni][2] = b2lo[ni]; acc[mi][ni][3] = b2hi[ni];
            }
        gemm_rApB<132, false, 4>(sA, sW2p, 16, acc, 0, wc, lane);
        GBAR(gr);                          // (2) h1 reads done

        // write h2 = silu(acc) into sA
#pragma unroll
        for (int mi = 0; mi < 2; ++mi) {
            int r = mi * 16 + g;
#pragma unroll
            for (int ni = 0; ni < 4; ++ni) {
                int c = wc * 32 + ni * 8 + 2 * t;
                *(float2*)&sA[r * 132 + c] =
                    make_float2(silu_f(acc[mi][ni][0]), silu_f(acc[mi][ni][1]));
                *(float2*)&sA[(r + 8) * 132 + c] =
                    make_float2(silu_f(acc[mi][ni][2]), silu_f(acc[mi][ni][3]));
            }
        }
        GBAR(gr);                          // (3) h2 complete

        // GEMM2: h3pre = h2 @ W5 + b5 (cvt A)
        float acc2[2][4][4];
#pragma unroll
        for (int mi = 0; mi < 2; ++mi)
#pragma unroll
            for (int ni = 0; ni < 4; ++ni) {
                acc2[mi][ni][0] = b5lo[ni]; acc2[mi][ni][1] = b5hi[ni];
                acc2[mi][ni][2] = b5lo[ni]; acc2[mi][ni][3] = b5hi[ni];
            }
        gemm_rApB<132, true, 4>(sA, sW5p, 16, acc2, 0, wc, lane);

        // scatter h2 -> g_hneigh (vector reduction atomics)
#pragma unroll
        for (int k = 0; k < 8; ++k) {
            int row = r0 + 4 * k;
            int d = __shfl_sync(0xffffffffu, de, row);
            const float4 v = *(const float4*)&sA[row * 132 + c4];
            float* p = &g_hneigh[(size_t)d * 128 + c4];
            asm volatile("red.global.add.v4.f32 [%0], {%1,%2,%3,%4};"
                         :: "l"(p), "f"(v.x), "f"(v.y), "f"(v.z), "f"(v.w) : "memory");
        }

        // cw[row] = sum_c silu(h3pre)*W6[c]
#pragma unroll
        for (int mi = 0; mi < 2; ++mi) {
            float pr0 = 0.f, pr1 = 0.f;
#pragma unroll
            for (int ni = 0; ni < 4; ++ni) {
                pr0 += silu_f(acc2[mi][ni][0]) * w6lo[ni] + silu_f(acc2[mi][ni][1]) * w6hi[ni];
                pr1 += silu_f(acc2[mi][ni][2]) * w6lo[ni] + silu_f(acc2[mi][ni][3]) * w6hi[ni];
            }
            pr0 += __shfl_xor_sync(0xffffffffu, pr0, 1);
            pr0 += __shfl_xor_sync(0xffffffffu, pr0, 2);
            pr1 += __shfl_xor_sync(0xffffffffu, pr1, 1);
            pr1 += __shfl_xor_sync(0xffffffffu, pr1, 2);
            if (t == 0) {
                int r = mi * 16 + g;
                atomicAdd(&sCW[pp * 32 + r], pr0);
                atomicAdd(&sCW[pp * 32 + r + 8], pr1);
            }
        }
        GBAR(gr);                          // (4) sCW complete, sA reads done

        if (wc == 0) {
            float cw = sCW[pp * 32 + lane];
            sCW[pp * 32 + lane] = 0.f;     // re-zero for reuse in 2 chunks
            float inv = 1.0f / (sqrtf(rr + 1e-6f) + 1e-6f);
            float cws = cw * inv;
            atomicAdd(&g_xsum[de * 3 + 0], cws * dxr);
            atomicAdd(&g_xsum[de * 3 + 1], cws * dyr);
            atomicAdd(&g_xsum[de * 3 + 2], cws * dzr);
        }
        // no loop-top barrier: sA free after (4); sCW buffer pp reused only
        // after two more (4)-barriers, past the zeroing above.
    }
}

// ---------------- k_node1: t1 = silu([nf|h_neigh] @ W3 + b3) -> g_t1 ----------------
__global__ void __launch_bounds__(512, 1)
k_node1(const float* __restrict__ nf, const float* __restrict__ W3,
        const float* __restrict__ b3) {
    extern __shared__ float sm[];
    float* sWa = sm;                       // 16384 (paired)
    float* sWb = sWa + 16384;              // 16384 (paired)
    float* sA  = sWb + 16384;              // 128*132

    const int tid = threadIdx.x, lane = tid & 31, wid = tid >> 5;
    const int wr = wid & 3, wc = wid >> 2;
    const int g = lane >> 2, t = lane & 3;

    load_paired(sWa, W3, tid, 512);
    load_paired(sWb, W3 + 16384, tid, 512);
    __syncthreads();

    float blo[4], bhi[4];
    {
        int cb = wc * 32 + 2 * t;
#pragma unroll
        for (int ni = 0; ni < 4; ++ni) {
            blo[ni] = __ldg(&b3[cb + ni * 8]);
            bhi[ni] = __ldg(&b3[cb + ni * 8 + 1]);
        }
    }

    const int ntiles = (NN + 127) / 128;
    for (int tile = blockIdx.x; tile < ntiles; tile += gridDim.x) {
        const int bn = tile * 128;
        for (int i = tid; i < 4096; i += 512) {
            int row = i >> 5, c4 = (i & 31) * 4;
            int n = bn + row;
            float4 v = make_float4(0.f, 0.f, 0.f, 0.f);
            if (n < NN) v = *(const float4*)&nf[(size_t)n * 128 + c4];
            float* p = &sA[row * 132 + c4];
            p[0] = tf32f(v.x); p[1] = tf32f(v.y); p[2] = tf32f(v.z); p[3] = tf32f(v.w);
        }
        __syncthreads();

        float acc[2][4][4];
#pragma unroll
        for (int mi = 0; mi < 2; ++mi)
#pragma unroll
            for (int ni = 0; ni < 4; ++ni) {
                acc[mi][ni][0] = blo[ni]; acc[mi][ni][1] = bhi[ni];
                acc[mi][ni][2] = blo[ni]; acc[mi][ni][3] = bhi[ni];
            }
        gemm_rApB<132, false, 4>(sA, sWa, 16, acc, wr, wc, lane);
        __syncthreads();
        for (int i = tid; i < 4096; i += 512) {
            int row = i >> 5, c4 = (i & 31) * 4;
            int n = bn + row;
            float4 v = make_float4(0.f, 0.f, 0.f, 0.f);
            if (n < NN) v = *(const float4*)&g_hneigh[(size_t)n * 128 + c4];
            float* p = &sA[row * 132 + c4];
            p[0] = tf32f(v.x); p[1] = tf32f(v.y); p[2] = tf32f(v.z); p[3] = tf32f(v.w);
        }
        __syncthreads();
        gemm_rApB<132, false, 4>(sA, sWb, 16, acc, wr, wc, lane);

#pragma unroll
        for (int mi = 0; mi < 2; ++mi) {
            int r = bn + wr * 32 + mi * 16 + g;
#pragma unroll
            for (int ni = 0; ni < 4; ++ni) {
                int c = wc * 32 + ni * 8 + 2 * t;
                if (r < NN)
                    *(float2*)&g_t1[(size_t)r * 128 + c] =
                        make_float2(tf32f(silu_f(acc[mi][ni][0])), tf32f(silu_f(acc[mi][ni][1])));
                if (r + 8 < NN)
                    *(float2*)&g_t1[(size_t)(r + 8) * 128 + c] =
                        make_float2(tf32f(silu_f(acc[mi][ni][2])), tf32f(silu_f(acc[mi][ni][3])));
            }
        }
        __syncthreads();
    }
}

// ---------------- k_node2: h = t1 @ W4 + b4 -> out ----------------
__global__ void __launch_bounds__(512, 1)
k_node2(const float* __restrict__ W4, const float* __restrict__ b4,
        float* __restrict__ outh) {
    extern __shared__ float sm[];
    float* sW = sm;                        // 16384 (paired)
    float* sA = sW + 16384;                // 128*132

    const int tid = threadIdx.x, lane = tid & 31, wid = tid >> 5;
    const int wr = wid & 3, wc = wid >> 2;
    const int g = lane >> 2, t = lane & 3;

    load_paired(sW, W4, tid, 512);
    __syncthreads();

    float blo[4], bhi[4];
    {
        int cb = wc * 32 + 2 * t;
#pragma unroll
        for (int ni = 0; ni < 4; ++ni) {
            blo[ni] = __ldg(&b4[cb + ni * 8]);
            bhi[ni] = __ldg(&b4[cb + ni * 8 + 1]);
        }
    }

    const int ntiles = (NN + 127) / 128;
    for (int tile = blockIdx.x; tile < ntiles; tile += gridDim.x) {
        const int bn = tile * 128;
        for (int i = tid; i < 4096; i += 512) {
            int row = i >> 5, c4 = (i & 31) * 4;
            int n = bn + row;
            float4 v = make_float4(0.f, 0.f, 0.f, 0.f);
            if (n < NN) v = *(const float4*)&g_t1[(size_t)n * 128 + c4];
            *(float4*)&sA[row * 132 + c4] = v;
        }
        __syncthreads();

        float acc[2][4][4];
#pragma unroll
        for (int mi = 0; mi < 2; ++mi)
#pragma unroll
            for (int ni = 0; ni < 4; ++ni) {
                acc[mi][ni][0] = blo[ni]; acc[mi][ni][1] = bhi[ni];
                acc[mi][ni][2] = blo[ni]; acc[mi][ni][3] = bhi[ni];
            }
        gemm_rApB<132, false, 4>(sA, sW, 16, acc, wr, wc, lane);

#pragma unroll
        for (int mi = 0; mi < 2; ++mi) {
            int r = bn + wr * 32 + mi * 16 + g;
#pragma unroll
            for (int ni = 0; ni < 4; ++ni) {
                int c = wc * 32 + ni * 8 + 2 * t;
                if (r < NN)
                    *(float2*)&outh[(size_t)r * 128 + c] =
                        make_float2(acc[mi][ni][0], acc[mi][ni][1]);
                if (r + 8 < NN)
                    *(float2*)&outh[(size_t)(r + 8) * 128 + c] =
                        make_float2(acc[mi][ni][2], acc[mi][ni][3]);
            }
        }
        __syncthreads();
    }
}

// ---------------- k_x / k_norm ----------------
__global__ void k_x(const float* __restrict__ coord, float* __restrict__ outx) {
    __shared__ float sred[6];
    int tid = threadIdx.x;
    if (tid < 6) sred[tid] = 0.f;
    __syncthreads();
    float ls[6] = {0.f, 0.f, 0.f, 0.f, 0.f, 0.f};
    int stride = gridDim.x * blockDim.x;
    for (int n = blockIdx.x * blockDim.x + tid; n < NN; n += stride) {
        float deg = fmaxf(g_deg[n], 1.0f);
        float invd = 1.0f / deg;
#pragma unroll
        for (int d = 0; d < 3; ++d) {
            float x = coord[n * 3 + d] + g_xsum[n * 3 + d] * invd;
            outx[n * 3 + d] = x;
            ls[d] += x;
            ls[3 + d] += x * x;
        }
    }
#pragma unroll
    for (int k = 0; k < 6; ++k) atomicAdd(&sred[k], ls[k]);
    __syncthreads();
    if (tid < 6) atomicAdd(&g_red[tid], sred[tid]);
}

// k_norm also computes mean/istd from g_red (absorbs old k_fin)
__global__ void k_norm(float* __restrict__ outx) {
    int stride = gridDim.x * blockDim.x;
    for (int i = blockIdx.x * blockDim.x + threadIdx.x; i < NN * 3; i += stride) {
        int d = i % 3;
        float mean = g_red[d] / (float)NN;
        float m2   = g_red[3 + d] / (float)NN;
        float var  = m2 - mean * mean;
        float istd = 1.0f / (sqrtf(var + 1e-6f) + 1e-6f);
        outx[i] = (outx[i] - mean) * istd;
    }
}

// ---------------- launch ----------------
extern "C" void kernel_launch(void* const* d_in, const int* in_sizes, int n_in,
                              void* d_out, int out_size) {
    const float* nf    = (const float*)d_in[0];
    const float* coord = (const float*)d_in[1];
    const int*   src   = (const int*)d_in[2];
    const int*   dst   = (const int*)d_in[3];
    const float* W1 = (const float*)d_in[4];
    const float* b1 = (const float*)d_in[5];
    const float* W2 = (const float*)d_in[6];
    const float* b2 = (const float*)d_in[7];
    const float* W3 = (const float*)d_in[8];
    const float* b3 = (const float*)d_in[9];
    const float* W4 = (const float*)d_in[10];
    const float* b4 = (const float*)d_in[11];
    const float* W5 = (const float*)d_in[12];
    const float* b5 = (const float*)d_in[13];
    const float* W6 = (const float*)d_in[14];

    float* outh = (float*)d_out;
    float* outx = outh + (size_t)NN * C;

    const int SM_NPRE = (16384 * 2 + 16896) * 4;
    const int SM_EDGE = (16384 * 2 + 16896 + 128 * 2 + 256) * 4;
    const int SM_N1   = (16384 * 2 + 16896) * 4;
    const int SM_N2   = (16384 + 16896) * 4;

    cudaFuncSetAttribute(k_npre,  cudaFuncAttributeMaxDynamicSharedMemorySize, SM_NPRE);
    cudaFuncSetAttribute(k_edge,  cudaFuncAttributeMaxDynamicSharedMemorySize, SM_EDGE);
    cudaFuncSetAttribute(k_node1, cudaFuncAttributeMaxDynamicSharedMemorySize, SM_N1);
    cudaFuncSetAttribute(k_node2, cudaFuncAttributeMaxDynamicSharedMemorySize, SM_N2);

    k_npre<<<148, 512, SM_NPRE>>>(nf, W1);
    k_edge<<<148, 512, SM_EDGE>>>(coord, src, dst, W1, b1, W2, b2, W5, b5, W6);
    k_node1<<<148, 512, SM_N1>>>(nf, W3, b3);
    k_node2<<<148, 512, SM_N2>>>(W4, b4, outh);
    k_x<<<160, 256>>>(coord, outx);
    k_norm<<<160, 256>>>(outx);
}

// round 14
// speedup vs baseline: 1.9964x; 1.0202x over previous
#include <cuda_runtime.h>
#include <cuda_bf16.h>
#include <math.h>

#define NN 50000
#define NE 800000
#define C  128

// ---------------- device scratch ----------------
static __device__ float g_P1[(size_t)NN * C];    // nf @ W1a
static __device__ float g_P2[(size_t)NN * C];    // nf @ W1b
static __device__ float g_t1[(size_t)NN * C];    // node hidden
static __device__ float g_hneigh[(size_t)NN * C];
static __device__ float g_xsum[NN * 3];
static __device__ float g_deg[NN];
static __device__ float g_red[16];

// silu via MUFU.TANH: sigma(x)=0.5*tanh(x/2)+0.5 -> silu=fma(h,tanh(h),h)
__device__ __forceinline__ float silu_f(float v) {
    float h = 0.5f * v, th;
    asm("tanh.approx.f32 %0, %1;" : "=f"(th) : "f"(h));
    return fmaf(h, th, h);
}
__device__ __forceinline__ float tf32f(float x) {
    unsigned u;
    asm("cvt.rna.tf32.f32 %0, %1;" : "=r"(u) : "f"(x));
    return __uint_as_float(u);
}
__device__ __forceinline__ unsigned fu(float x) { return __float_as_uint(x); }

__device__ __forceinline__ void mma8(float* d, const unsigned* a, unsigned b0, unsigned b1) {
    asm volatile(
        "mma.sync.aligned.m16n8k8.row.col.f32.tf32.tf32.f32 "
        "{%0,%1,%2,%3}, {%4,%5,%6,%7}, {%8,%9}, {%0,%1,%2,%3};"
        : "+f"(d[0]), "+f"(d[1]), "+f"(d[2]), "+f"(d[3])
        : "r"(a[0]), "r"(a[1]), "r"(a[2]), "r"(a[3]), "r"(b0), "r"(b1));
}

#define GBAR(gr) asm volatile("bar.sync %0, 128;" :: "r"((gr) + 1) : "memory")

// =============== paired-k W layout ===============
// sWp[(kc*128 + c)*8 + 2*(k&3) + ((k>>2)&1)] holds W[k][c], kc = k>>3.
// B-fragment (k=t, k=t+4) for col c is one aligned float2.

template<int SA, bool CVTA, int NI>
__device__ __forceinline__ void gemm_rApB(const float* __restrict__ sA,
                                          const float* __restrict__ sWp,
                                          int kchunks, float (&acc)[2][NI][4],
                                          int wr, int wc, int lane) {
    const int g = lane >> 2, t = lane & 3;
    const float* ar = sA + (wr * 32 + g) * SA + t;
    const float* bb = sWp + (wc * (NI * 8) + g) * 8 + 2 * t;
#pragma unroll 4
    for (int kc = 0; kc < kchunks; ++kc) {
        const float* ap = ar + kc * 8;
        float a00 = ap[0],       a01 = ap[8 * SA],       a02 = ap[4],       a03 = ap[8 * SA + 4];
        float a10 = ap[16 * SA], a11 = ap[24 * SA],      a12 = ap[16 * SA + 4], a13 = ap[24 * SA + 4];
        if (CVTA) {
            a00 = tf32f(a00); a01 = tf32f(a01); a02 = tf32f(a02); a03 = tf32f(a03);
            a10 = tf32f(a10); a11 = tf32f(a11); a12 = tf32f(a12); a13 = tf32f(a13);
        }
        unsigned A0[4] = {fu(a00), fu(a01), fu(a02), fu(a03)};
        unsigned A1[4] = {fu(a10), fu(a11), fu(a12), fu(a13)};
        const float* bp = bb + kc * 1024;
#pragma unroll
        for (int ni = 0; ni < NI; ++ni) {
            float2 b = *(const float2*)(bp + ni * 64);
            mma8(acc[0][ni], A0, fu(b.x), fu(b.y));
            mma8(acc[1][ni], A1, fu(b.x), fu(b.y));
        }
    }
}

// load W[16384] (row-major [128][128]) into paired layout with tf32 rounding
__device__ __forceinline__ void load_paired(float* sWp, const float* W, int tid, int nthr) {
    for (int i = tid; i < 16384; i += nthr) {
        int k = i >> 7, c = i & 127;
        int pos = ((k >> 3) * 128 + c) * 8 + 2 * (k & 3) + ((k >> 2) & 1);
        sWp[pos] = tf32f(W[i]);
    }
}

// ---------------- k_npre: zero accumulators, then P1/P2 ----------------
__global__ void __launch_bounds__(512, 1)
k_npre(const float* __restrict__ nf, const float* __restrict__ W1) {
    extern __shared__ float sm[];
    float* sWa = sm;                       // 16384 (paired)
    float* sWb = sWa + 16384;              // 16384 (paired)
    float* sA  = sWb + 16384;              // 128*132 = 16896

    const int tid = threadIdx.x, lane = tid & 31, wid = tid >> 5;
    const int wr = wid & 3, wc = wid >> 2;
    const int g = lane >> 2, t = lane & 3;

    {
        const long NC = (long)NN * C, N3 = NN * 3;
        const long TOT = NC + N3 + NN + 16;
        long stride = (long)gridDim.x * blockDim.x;
        for (long i = (long)blockIdx.x * blockDim.x + tid; i < TOT; i += stride) {
            if (i < NC) g_hneigh[i] = 0.f;
            else if (i < NC + N3) g_xsum[i - NC] = 0.f;
            else if (i < NC + N3 + NN) g_deg[i - NC - N3] = 0.f;
            else g_red[i - NC - N3 - NN] = 0.f;
        }
    }

    load_paired(sWa, W1, tid, 512);
    load_paired(sWb, W1 + 16384, tid, 512);
    __syncthreads();

    const int ntiles = (NN + 127) / 128;
    for (int tile = blockIdx.x; tile < ntiles; tile += gridDim.x) {
        const int bn = tile * 128;
        for (int i = tid; i < 4096; i += 512) {
            int row = i >> 5, c4 = (i & 31) * 4;
            int n = bn + row;
            float4 v = make_float4(0.f, 0.f, 0.f, 0.f);
            if (n < NN) v = *(const float4*)&nf[(size_t)n * 128 + c4];
            float* p = &sA[row * 132 + c4];
            p[0] = tf32f(v.x); p[1] = tf32f(v.y); p[2] = tf32f(v.z); p[3] = tf32f(v.w);
        }
        __syncthreads();

        float acc[2][4][4];
#pragma unroll
        for (int mi = 0; mi < 2; ++mi)
#pragma unroll
            for (int ni = 0; ni < 4; ++ni)
#pragma unroll
                for (int q = 0; q < 4; ++q) acc[mi][ni][q] = 0.f;
        gemm_rApB<132, false, 4>(sA, sWa, 16, acc, wr, wc, lane);
#pragma unroll
        for (int mi = 0; mi < 2; ++mi) {
            int r = bn + wr * 32 + mi * 16 + g;
#pragma unroll
            for (int ni = 0; ni < 4; ++ni) {
                int c = wc * 32 + ni * 8 + 2 * t;
                if (r < NN)
                    *(float2*)&g_P1[(size_t)r * 128 + c] = make_float2(acc[mi][ni][0], acc[mi][ni][1]);
                if (r + 8 < NN)
                    *(float2*)&g_P1[(size_t)(r + 8) * 128 + c] = make_float2(acc[mi][ni][2], acc[mi][ni][3]);
            }
        }
#pragma unroll
        for (int mi = 0; mi < 2; ++mi)
#pragma unroll
            for (int ni = 0; ni < 4; ++ni)
#pragma unroll
                for (int q = 0; q < 4; ++q) acc[mi][ni][q] = 0.f;
        gemm_rApB<132, false, 4>(sA, sWb, 16, acc, wr, wc, lane);
#pragma unroll
        for (int mi = 0; mi < 2; ++mi) {
            int r = bn + wr * 32 + mi * 16 + g;
#pragma unroll
            for (int ni = 0; ni < 4; ++ni) {
                int c = wc * 32 + ni * 8 + 2 * t;
                if (r < NN)
                    *(float2*)&g_P2[(size_t)r * 128 + c] = make_float2(acc[mi][ni][0], acc[mi][ni][1]);
                if (r + 8 < NN)
                    *(float2*)&g_P2[(size_t)(r + 8) * 128 + c] = make_float2(acc[mi][ni][2], acc[mi][ni][3]);
            }
        }
        __syncthreads();
    }
}

// ---------------- k_edge: 4 groups + edge-metadata software pipeline ----------------
__global__ void __launch_bounds__(512, 1)
k_edge(const float* __restrict__ coord,
       const int* __restrict__ src, const int* __restrict__ dst,
       const float* __restrict__ W1, const float* __restrict__ b1,
       const float* __restrict__ W2, const float* __restrict__ b2,
       const float* __restrict__ W5, const float* __restrict__ b5,
       const float* __restrict__ W6) {
    extern __shared__ float sm[];
    float* sW2p = sm;                      // 16384 (paired)
    float* sW5p = sW2p + 16384;            // 16384 (paired)
    float* sAall = sW5p + 16384;           // 4 * 32*132 = 16896
    float* sWr  = sAall + 16896;           // 128
    float* sB1  = sWr + 128;               // 128
    float* sCWA = sB1 + 128;               // 4 groups * 2 buf * 32 = 256

    const int tid = threadIdx.x, lane = tid & 31, wid = tid >> 5;
    const int gr = wid >> 2;               // group 0..3 (4 warps across 4 SMSPs)
    const int wc = wid & 3;                // column warp within group
    const int g = lane >> 2, t = lane & 3;
    const int gt = wc * 32 + lane;         // group-local thread 0..127

    float* sA  = sAall + gr * 4224;        // 32*132 per group
    float* sCW = sCWA + gr * 64;           // 2 x 32 double buffer

    load_paired(sW2p, W2, tid, 512);
    load_paired(sW5p, W5, tid, 512);
    if (tid < 128) { sWr[tid] = W1[256 * 128 + tid]; sB1[tid] = b1[tid]; }
    if (tid < 256) sCWA[tid] = 0.f;
    __syncthreads();

    float b2lo[4], b2hi[4], b5lo[4], b5hi[4], w6lo[4], w6hi[4];
    {
        int cb = wc * 32 + 2 * t;
#pragma unroll
        for (int ni = 0; ni < 4; ++ni) {
            b2lo[ni] = __ldg(&b2[cb + ni * 8]); b2hi[ni] = __ldg(&b2[cb + ni * 8 + 1]);
            b5lo[ni] = __ldg(&b5[cb + ni * 8]); b5hi[ni] = __ldg(&b5[cb + ni * 8 + 1]);
            w6lo[ni] = __ldg(&W6[cb + ni * 8]); w6hi[ni] = __ldg(&W6[cb + ni * 8 + 1]);
        }
    }

    const int c4 = (gt & 31) * 4;          // this thread's column (fixed)
    const int r0 = gt >> 5;                // row phase (0..3)
    const float4 w4 = *(const float4*)&sWr[c4];
    const float4 bv = *(const float4*)&sB1[c4];

    const int nchunks = NE / 32;           // 25000
    const int gstride = gridDim.x * 4;

    // prologue: load metadata for the first chunk
    int chunk = blockIdx.x * 4 + gr;
    int se = 0, de = 0; float dxr = 0.f, dyr = 0.f, dzr = 0.f, rr = 0.f;
    if (chunk < nchunks) {
        int e = chunk * 32 + lane;
        se = __ldg(&src[e]); de = __ldg(&dst[e]);
        dxr = coord[se * 3 + 0] - coord[de * 3 + 0];
        dyr = coord[se * 3 + 1] - coord[de * 3 + 1];
        dzr = coord[se * 3 + 2] - coord[de * 3 + 2];
        rr = dxr * dxr + dyr * dyr + dzr * dzr;
    }

    int pp = 0;                            // sCW buffer parity
    for (; chunk < nchunks; pp ^= 1) {
        const int nchunk = chunk + gstride;
        if (wc == 0) atomicAdd(&g_deg[de], 1.0f);

        // gather-assemble h1 (32x128) into sA, 4-row load batches for MLP
#pragma unroll
        for (int half = 0; half < 2; ++half) {
            float4 p1v[4], p2v[4]; float rv[4];
#pragma unroll
            for (int k = 0; k < 4; ++k) {
                int row = r0 + 4 * (half * 4 + k);
                int s = __shfl_sync(0xffffffffu, se, row);
                int d = __shfl_sync(0xffffffffu, de, row);
                rv[k] = __shfl_sync(0xffffffffu, rr, row);
                p1v[k] = *(const float4*)&g_P1[(size_t)s * 128 + c4];
                p2v[k] = *(const float4*)&g_P2[(size_t)d * 128 + c4];
            }
#pragma unroll
            for (int k = 0; k < 4; ++k) {
                int row = r0 + 4 * (half * 4 + k);
                float4 o;
                o.x = tf32f(silu_f(p1v[k].x + p2v[k].x + rv[k] * w4.x + bv.x));
                o.y = tf32f(silu_f(p1v[k].y + p2v[k].y + rv[k] * w4.y + bv.y));
                o.z = tf32f(silu_f(p1v[k].z + p2v[k].z + rv[k] * w4.z + bv.z));
                o.w = tf32f(silu_f(p1v[k].w + p2v[k].w + rv[k] * w4.w + bv.w));
                *(float4*)&sA[row * 132 + c4] = o;
            }
        }
        GBAR(gr);                          // (1) h1 complete

        // prefetch next chunk's metadata (independent of sA; overlaps GEMMs)
        int se2 = 0, de2 = 0; float dxr2 = 0.f, dyr2 = 0.f, dzr2 = 0.f, rr2 = 0.f;
        if (nchunk < nchunks) {
            int e2 = nchunk * 32 + lane;
            se2 = __ldg(&src[e2]); de2 = __ldg(&dst[e2]);
            dxr2 = coord[se2 * 3 + 0] - coord[de2 * 3 + 0];
            dyr2 = coord[se2 * 3 + 1] - coord[de2 * 3 + 1];
            dzr2 = coord[se2 * 3 + 2] - coord[de2 * 3 + 2];
            rr2 = dxr2 * dxr2 + dyr2 * dyr2 + dzr2 * dzr2;
        }

        // GEMM1: h2pre = h1 @ W2 + b2 (warp owns 32x32 block)
        float acc[2][4][4];
#pragma unroll
        for (int mi = 0; mi < 2; ++mi)
#pragma unroll
            for (int ni = 0; ni < 4; ++ni) {
                acc[mi][ni][0] = b2lo[ni]; acc[mi][ni][1] = b2hi[ni];
                acc[mi][ni][2] = b2lo[ni]; acc[mi][ni][3] = b2hi[ni];
            }
        gemm_rApB<132, false, 4>(sA, sW2p, 16, acc, 0, wc, lane);
        GBAR(gr);                          // (2) h1 reads done

        // write h2 = silu(acc) into sA
#pragma unroll
        for (int mi = 0; mi < 2; ++mi) {
            int r = mi * 16 + g;
#pragma unroll
            for (int ni = 0; ni < 4; ++ni) {
                int c = wc * 32 + ni * 8 + 2 * t;
                *(float2*)&sA[r * 132 + c] =
                    make_float2(silu_f(acc[mi][ni][0]), silu_f(acc[mi][ni][1]));
                *(float2*)&sA[(r + 8) * 132 + c] =
                    make_float2(silu_f(acc[mi][ni][2]), silu_f(acc[mi][ni][3]));
            }
        }
        GBAR(gr);                          // (3) h2 complete

        // GEMM2: h3pre = h2 @ W5 + b5 (cvt A)
        float acc2[2][4][4];
#pragma unroll
        for (int mi = 0; mi < 2; ++mi)
#pragma unroll
            for (int ni = 0; ni < 4; ++ni) {
                acc2[mi][ni][0] = b5lo[ni]; acc2[mi][ni][1] = b5hi[ni];
                acc2[mi][ni][2] = b5lo[ni]; acc2[mi][ni][3] = b5hi[ni];
            }
        gemm_rApB<132, true, 4>(sA, sW5p, 16, acc2, 0, wc, lane);

        // scatter h2 -> g_hneigh (vector reduction atomics)
#pragma unroll
        for (int k = 0; k < 8; ++k) {
            int row = r0 + 4 * k;
            int d = __shfl_sync(0xffffffffu, de, row);
            const float4 v = *(const float4*)&sA[row * 132 + c4];
            float* p = &g_hneigh[(size_t)d * 128 + c4];
            asm volatile("red.global.add.v4.f32 [%0], {%1,%2,%3,%4};"
                         :: "l"(p), "f"(v.x), "f"(v.y), "f"(v.z), "f"(v.w) : "memory");
        }

        // cw[row] = sum_c silu(h3pre)*W6[c]
#pragma unroll
        for (int mi = 0; mi < 2; ++mi) {
            float pr0 = 0.f, pr1 = 0.f;
#pragma unroll
            for (int ni = 0; ni < 4; ++ni) {
                pr0 += silu_f(acc2[mi][ni][0]) * w6lo[ni] + silu_f(acc2[mi][ni][1]) * w6hi[ni];
                pr1 += silu_f(acc2[mi][ni][2]) * w6lo[ni] + silu_f(acc2[mi][ni][3]) * w6hi[ni];
            }
            pr0 += __shfl_xor_sync(0xffffffffu, pr0, 1);
            pr0 += __shfl_xor_sync(0xffffffffu, pr0, 2);
            pr1 += __shfl_xor_sync(0xffffffffu, pr1, 1);
            pr1 += __shfl_xor_sync(0xffffffffu, pr1, 2);
            if (t == 0) {
                int r = mi * 16 + g;
                atomicAdd(&sCW[pp * 32 + r], pr0);
                atomicAdd(&sCW[pp * 32 + r + 8], pr1);
            }
        }
        GBAR(gr);                          // (4) sCW complete, sA reads done

        if (wc == 0) {
            float cw = sCW[pp * 32 + lane];
            sCW[pp * 32 + lane] = 0.f;     // re-zero for reuse in 2 chunks
            float inv = 1.0f / (sqrtf(rr + 1e-6f) + 1e-6f);
            float cws = cw * inv;
            atomicAdd(&g_xsum[de * 3 + 0], cws * dxr);
            atomicAdd(&g_xsum[de * 3 + 1], cws * dyr);
            atomicAdd(&g_xsum[de * 3 + 2], cws * dzr);
        }
        // rotate prefetched metadata
        se = se2; de = de2; dxr = dxr2; dyr = dyr2; dzr = dzr2; rr = rr2;
        chunk = nchunk;
        // no loop-top barrier: sA free after (4); sCW buffer pp reused only
        // after two more (4)-barriers, past the zeroing above.
    }
}

// ---------------- k_node1: k_x prologue + t1 = silu([nf|h_neigh]@W3+b3) ----------------
__global__ void __launch_bounds__(512, 1)
k_node1(const float* __restrict__ nf, const float* __restrict__ W3,
        const float* __restrict__ b3, const float* __restrict__ coord,
        float* __restrict__ outx) {
    extern __shared__ float sm[];
    float* sWa = sm;                       // 16384 (paired)
    float* sWb = sWa + 16384;              // 16384 (paired)
    float* sA  = sWb + 16384;              // 128*132

    const int tid = threadIdx.x, lane = tid & 31, wid = tid >> 5;
    const int wr = wid & 3, wc = wid >> 2;
    const int g = lane >> 2, t = lane & 3;

    // --- fused k_x: x = coord + xsum/deg; accumulate mean/var sums ---
    {
        __shared__ float sred[6];
        if (tid < 6) sred[tid] = 0.f;
        __syncthreads();
        float ls[6] = {0.f, 0.f, 0.f, 0.f, 0.f, 0.f};
        int stride = gridDim.x * blockDim.x;
        for (int n = blockIdx.x * blockDim.x + tid; n < NN; n += stride) {
            float deg = fmaxf(g_deg[n], 1.0f);
            float invd = 1.0f / deg;
#pragma unroll
            for (int d = 0; d < 3; ++d) {
                float x = coord[n * 3 + d] + g_xsum[n * 3 + d] * invd;
                outx[n * 3 + d] = x;
                ls[d] += x;
                ls[3 + d] += x * x;
            }
        }
#pragma unroll
        for (int k = 0; k < 6; ++k) atomicAdd(&sred[k], ls[k]);
        __syncthreads();
        if (tid < 6) atomicAdd(&g_red[tid], sred[tid]);
    }

    load_paired(sWa, W3, tid, 512);
    load_paired(sWb, W3 + 16384, tid, 512);
    __syncthreads();

    float blo[4], bhi[4];
    {
        int cb = wc * 32 + 2 * t;
#pragma unroll
        for (int ni = 0; ni < 4; ++ni) {
            blo[ni] = __ldg(&b3[cb + ni * 8]);
            bhi[ni] = __ldg(&b3[cb + ni * 8 + 1]);
        }
    }

    const int ntiles = (NN + 127) / 128;
    for (int tile = blockIdx.x; tile < ntiles; tile += gridDim.x) {
        const int bn = tile * 128;
        for (int i = tid; i < 4096; i += 512) {
            int row = i >> 5, c4 = (i & 31) * 4;
            int n = bn + row;
            float4 v = make_float4(0.f, 0.f, 0.f, 0.f);
            if (n < NN) v = *(const float4*)&nf[(size_t)n * 128 + c4];
            float* p = &sA[row * 132 + c4];
            p[0] = tf32f(v.x); p[1] = tf32f(v.y); p[2] = tf32f(v.z); p[3] = tf32f(v.w);
        }
        __syncthreads();

        float acc[2][4][4];
#pragma unroll
        for (int mi = 0; mi < 2; ++mi)
#pragma unroll
            for (int ni = 0; ni < 4; ++ni) {
                acc[mi][ni][0] = blo[ni]; acc[mi][ni][1] = bhi[ni];
                acc[mi][ni][2] = blo[ni]; acc[mi][ni][3] = bhi[ni];
            }
        gemm_rApB<132, false, 4>(sA, sWa, 16, acc, wr, wc, lane);
        __syncthreads();
        for (int i = tid; i < 4096; i += 512) {
            int row = i >> 5, c4 = (i & 31) * 4;
            int n = bn + row;
            float4 v = make_float4(0.f, 0.f, 0.f, 0.f);
            if (n < NN) v = *(const float4*)&g_hneigh[(size_t)n * 128 + c4];
            float* p = &sA[row * 132 + c4];
            p[0] = tf32f(v.x); p[1] = tf32f(v.y); p[2] = tf32f(v.z); p[3] = tf32f(v.w);
        }
        __syncthreads();
        gemm_rApB<132, false, 4>(sA, sWb, 16, acc, wr, wc, lane);

#pragma unroll
        for (int mi = 0; mi < 2; ++mi) {
            int r = bn + wr * 32 + mi * 16 + g;
#pragma unroll
            for (int ni = 0; ni < 4; ++ni) {
                int c = wc * 32 + ni * 8 + 2 * t;
                if (r < NN)
                    *(float2*)&g_t1[(size_t)r * 128 + c] =
                        make_float2(tf32f(silu_f(acc[mi][ni][0])), tf32f(silu_f(acc[mi][ni][1])));
                if (r + 8 < NN)
                    *(float2*)&g_t1[(size_t)(r + 8) * 128 + c] =
                        make_float2(tf32f(silu_f(acc[mi][ni][2])), tf32f(silu_f(acc[mi][ni][3])));
            }
        }
        __syncthreads();
    }
}

// ---------------- k_node2: k_norm prologue + h = t1 @ W4 + b4 -> out ----------------
__global__ void __launch_bounds__(512, 1)
k_node2(const float* __restrict__ W4, const float* __restrict__ b4,
        float* __restrict__ outh, float* __restrict__ outx) {
    extern __shared__ float sm[];
    float* sW = sm;                        // 16384 (paired)
    float* sA = sW + 16384;                // 128*132

    const int tid = threadIdx.x, lane = tid & 31, wid = tid >> 5;
    const int wr = wid & 3, wc = wid >> 2;
    const int g = lane >> 2, t = lane & 3;

    // --- fused k_norm: normalize x (g_red complete after k_node1) ---
    {
        float mean0 = g_red[0] / (float)NN, mean1 = g_red[1] / (float)NN, mean2 = g_red[2] / (float)NN;
        float v0 = g_red[3] / (float)NN - mean0 * mean0;
        float v1 = g_red[4] / (float)NN - mean1 * mean1;
        float v2 = g_red[5] / (float)NN - mean2 * mean2;
        float is0 = 1.0f / (sqrtf(v0 + 1e-6f) + 1e-6f);
        float is1 = 1.0f / (sqrtf(v1 + 1e-6f) + 1e-6f);
        float is2 = 1.0f / (sqrtf(v2 + 1e-6f) + 1e-6f);
        int stride = gridDim.x * blockDim.x;
        for (int n = blockIdx.x * blockDim.x + tid; n < NN; n += stride) {
            outx[n * 3 + 0] = (outx[n * 3 + 0] - mean0) * is0;
            outx[n * 3 + 1] = (outx[n * 3 + 1] - mean1) * is1;
            outx[n * 3 + 2] = (outx[n * 3 + 2] - mean2) * is2;
        }
    }

    load_paired(sW, W4, tid, 512);
    __syncthreads();

    float blo[4], bhi[4];
    {
        int cb = wc * 32 + 2 * t;
#pragma unroll
        for (int ni = 0; ni < 4; ++ni) {
            blo[ni] = __ldg(&b4[cb + ni * 8]);
            bhi[ni] = __ldg(&b4[cb + ni * 8 + 1]);
        }
    }

    const int ntiles = (NN + 127) / 128;
    for (int tile = blockIdx.x; tile < ntiles; tile += gridDim.x) {
        const int bn = tile * 128;
        for (int i = tid; i < 4096; i += 512) {
            int row = i >> 5, c4 = (i & 31) * 4;
            int n = bn + row;
            float4 v = make_float4(0.f, 0.f, 0.f, 0.f);
            if (n < NN) v = *(const float4*)&g_t1[(size_t)n * 128 + c4];
            *(float4*)&sA[row * 132 + c4] = v;
        }
        __syncthreads();

        float acc[2][4][4];
#pragma unroll
        for (int mi = 0; mi < 2; ++mi)
#pragma unroll
            for (int ni = 0; ni < 4; ++ni) {
                acc[mi][ni][0] = blo[ni]; acc[mi][ni][1] = bhi[ni];
                acc[mi][ni][2] = blo[ni]; acc[mi][ni][3] = bhi[ni];
            }
        gemm_rApB<132, false, 4>(sA, sW, 16, acc, wr, wc, lane);

#pragma unroll
        for (int mi = 0; mi < 2; ++mi) {
            int r = bn + wr * 32 + mi * 16 + g;
#pragma unroll
            for (int ni = 0; ni < 4; ++ni) {
                int c = wc * 32 + ni * 8 + 2 * t;
                if (r < NN)
                    *(float2*)&outh[(size_t)r * 128 + c] =
                        make_float2(acc[mi][ni][0], acc[mi][ni][1]);
                if (r + 8 < NN)
                    *(float2*)&outh[(size_t)(r + 8) * 128 + c] =
                        make_float2(acc[mi][ni][2], acc[mi][ni][3]);
            }
        }
        __syncthreads();
    }
}

// ---------------- launch ----------------
extern "C" void kernel_launch(void* const* d_in, const int* in_sizes, int n_in,
                              void* d_out, int out_size) {
    const float* nf    = (const float*)d_in[0];
    const float* coord = (const float*)d_in[1];
    const int*   src   = (const int*)d_in[2];
    const int*   dst   = (const int*)d_in[3];
    const float* W1 = (const float*)d_in[4];
    const float* b1 = (const float*)d_in[5];
    const float* W2 = (const float*)d_in[6];
    const float* b2 = (const float*)d_in[7];
    const float* W3 = (const float*)d_in[8];
    const float* b3 = (const float*)d_in[9];
    const float* W4 = (const float*)d_in[10];
    const float* b4 = (const float*)d_in[11];
    const float* W5 = (const float*)d_in[12];
    const float* b5 = (const float*)d_in[13];
    const float* W6 = (const float*)d_in[14];

    float* outh = (float*)d_out;
    float* outx = outh + (size_t)NN * C;

    const int SM_NPRE = (16384 * 2 + 16896) * 4;
    const int SM_EDGE = (16384 * 2 + 16896 + 128 * 2 + 256) * 4;
    const int SM_N1   = (16384 * 2 + 16896) * 4;
    const int SM_N2   = (16384 + 16896) * 4;

    cudaFuncSetAttribute(k_npre,  cudaFuncAttributeMaxDynamicSharedMemorySize, SM_NPRE);
    cudaFuncSetAttribute(k_edge,  cudaFuncAttributeMaxDynamicSharedMemorySize, SM_EDGE);
    cudaFuncSetAttribute(k_node1, cudaFuncAttributeMaxDynamicSharedMemorySize, SM_N1);
    cudaFuncSetAttribute(k_node2, cudaFuncAttributeMaxDynamicSharedMemorySize, SM_N2);

    k_npre<<<148, 512, SM_NPRE>>>(nf, W1);
    k_edge<<<148, 512, SM_EDGE>>>(coord, src, dst, W1, b1, W2, b2, W5, b5, W6);
    k_node1<<<148, 512, SM_N1>>>(nf, W3, b3, coord, outx);
    k_node2<<<148, 512, SM_N2>>>(W4, b4, outh, outx);
}